// round 3
// baseline (speedup 1.0000x reference)
#include <cuda_runtime.h>
#include <math.h>

// Problem constants
#define D_MODEL 1024
#define N_BATCH 4
#define SEQ     4096
#define HEADS   16
#define HD      64
#define NH      (N_BATCH * HEADS)        // 64
#define M_TOTAL (N_BATCH * SEQ)          // 16384

typedef unsigned long long ull;

// ---------------- scratch (device globals: no allocation allowed) ----------
__device__ float g_Q [M_TOTAL * D_MODEL];   // Q_lin  (elu+1 applied)
__device__ float g_K [M_TOTAL * D_MODEL];   // K_lin  (elu+1 applied)
__device__ float g_V [M_TOTAL * D_MODEL];   // V projection
__device__ float g_VL[M_TOTAL * D_MODEL];   // attention output (pre-Wo)
__device__ float g_KV[NH * HD * HD];        // per-(n,h) KV[m][d]
__device__ float g_KS[NH * HD];             // per-(n,h) K_sum[d]

// ---------------- packed f32x2 helpers (Blackwell FFMA2) -------------------
__device__ __forceinline__ void fma2(ull& d, ull a, ull b) {
    asm("fma.rn.f32x2 %0, %1, %2, %3;" : "=l"(d) : "l"(a), "l"(b), "l"(d));
}
__device__ __forceinline__ ull dup2(float x) {
    ull r; asm("mov.b64 %0, {%1, %1};" : "=l"(r) : "f"(x)); return r;
}
__device__ __forceinline__ float2 unpk(ull a) {
    float2 r; asm("mov.b64 {%0, %1}, %2;" : "=f"(r.x), "=f"(r.y) : "l"(a));
    return r;
}

// ---------------- generic fp32 GEMM: C = A[MxK] * B[KxN] + bias (+elu+1) ---
// BM=128, BN=128, BK=8, 256 threads, 8x8 per thread, f32x2 accumulation.
#define GBM 128
#define GBN 128
#define GBK 8

__global__ __launch_bounds__(256, 2)
void gemm_bias_act(const float* __restrict__ A, const float* __restrict__ B,
                   const float* __restrict__ bias, float* __restrict__ C,
                   int M, int N, int K, int act)
{
    __shared__ float As[GBK][GBM];   // transposed: As[k][m]
    __shared__ float Bs[GBK][GBN];

    const int tid = threadIdx.x;
    const int tx  = tid & 15;        // N direction (8 cols each)
    const int ty  = tid >> 4;        // M direction (8 rows each)

    const int brow0 = blockIdx.y * GBM;
    const int bcol0 = blockIdx.x * GBN;

    // global load mapping
    const int a_r = tid >> 1;            // 0..127
    const int a_c = (tid & 1) * 4;       // 0 or 4
    const int b_r = tid >> 5;            // 0..7
    const int b_c = (tid & 31) * 4;      // 0..124

    const float* Ag = A + (size_t)(brow0 + a_r) * K + a_c;
    const float* Bg = B + (size_t)b_r * N + bcol0 + b_c;

    ull acc[8][4];
    #pragma unroll
    for (int i = 0; i < 8; i++)
        #pragma unroll
        for (int j = 0; j < 4; j++) acc[i][j] = 0ull;

    const int nt = K / GBK;
    float4 apf = *(const float4*)Ag;
    float4 bpf = *(const float4*)Bg;

    for (int t = 0; t < nt; t++) {
        // stage current tile into smem
        As[a_c + 0][a_r] = apf.x;
        As[a_c + 1][a_r] = apf.y;
        As[a_c + 2][a_r] = apf.z;
        As[a_c + 3][a_r] = apf.w;
        *(float4*)&Bs[b_r][b_c] = bpf;
        __syncthreads();

        // prefetch next tile
        if (t + 1 < nt) {
            apf = *(const float4*)(Ag + (size_t)(t + 1) * GBK);
            bpf = *(const float4*)(Bg + (size_t)(t + 1) * GBK * N);
        }

        #pragma unroll
        for (int k = 0; k < GBK; k++) {
            const float4 a0 = *(const float4*)&As[k][ty * 8];
            const float4 a1 = *(const float4*)&As[k][ty * 8 + 4];
            const ull*  bp  = (const ull*)&Bs[k][tx * 8];
            const ull b0 = bp[0], b1 = bp[1], b2 = bp[2], b3 = bp[3];
            float am[8] = {a0.x, a0.y, a0.z, a0.w, a1.x, a1.y, a1.z, a1.w};
            #pragma unroll
            for (int i = 0; i < 8; i++) {
                const ull av = dup2(am[i]);
                fma2(acc[i][0], av, b0);
                fma2(acc[i][1], av, b1);
                fma2(acc[i][2], av, b2);
                fma2(acc[i][3], av, b3);
            }
        }
        __syncthreads();
    }

    // epilogue: bias, optional elu+1, store
    float bv8[8];
    *(float4*)&bv8[0] = *(const float4*)(bias + bcol0 + tx * 8);
    *(float4*)&bv8[4] = *(const float4*)(bias + bcol0 + tx * 8 + 4);

    #pragma unroll
    for (int i = 0; i < 8; i++) {
        float r[8];
        #pragma unroll
        for (int j = 0; j < 4; j++) {
            float2 p = unpk(acc[i][j]);
            r[2 * j]     = p.x;
            r[2 * j + 1] = p.y;
        }
        #pragma unroll
        for (int j = 0; j < 8; j++) {
            float v = r[j] + bv8[j];
            if (act) v = (v > 0.f) ? (v + 1.f) : expf(v);   // elu(v)+1
            r[j] = v;
        }
        float* cp = C + (size_t)(brow0 + ty * 8 + i) * N + bcol0 + tx * 8;
        *(float4*)cp       = make_float4(r[0], r[1], r[2], r[3]);
        *(float4*)(cp + 4) = make_float4(r[4], r[5], r[6], r[7]);
    }
}

// ---------------- zero scratch -------------------------------------------
__global__ void zero_kernel(float* p, int n)
{
    int i = blockIdx.x * blockDim.x + threadIdx.x;
    if (i < n) p[i] = 0.f;
}

// ---------------- KV[m][d] = sum_s K[s][d] * V[s][m] per (n,h) -------------
// grid (NH=64, SPLITS=8), 256 threads. Split-S partials via fp32 atomics.
__global__ void kv_kernel(const float* __restrict__ Kl, const float* __restrict__ Vb,
                          float* __restrict__ KV)
{
    __shared__ float Ks[8][64];
    __shared__ float Vs[8][64];

    const int nh = blockIdx.x;
    const int n  = nh >> 4;
    const int h  = nh & 15;
    const int t  = threadIdx.x;
    const int m  = t >> 2;              // 0..63
    const int d0 = (t & 3) << 4;        // 0,16,32,48

    const size_t base = (size_t)n * SEQ * D_MODEL + (size_t)h * HD;
    const int s0 = blockIdx.y * 512;

    // cooperative load mapping: 8 rows x 64 cols, float2 per thread
    const int lr = t >> 5;              // 0..7
    const int lc = (t & 31) * 2;        // 0..62

    ull acc[8];
    #pragma unroll
    for (int j = 0; j < 8; j++) acc[j] = 0ull;

    for (int s = s0; s < s0 + 512; s += 8) {
        const float2 kx = *(const float2*)(Kl + base + (size_t)(s + lr) * D_MODEL + lc);
        const float2 vx = *(const float2*)(Vb + base + (size_t)(s + lr) * D_MODEL + lc);
        __syncthreads();
        *(float2*)&Ks[lr][lc] = kx;
        *(float2*)&Vs[lr][lc] = vx;
        __syncthreads();
        #pragma unroll
        for (int ss = 0; ss < 8; ss++) {
            const ull vv = dup2(Vs[ss][m]);
            const ull* kp = (const ull*)&Ks[ss][d0];
            #pragma unroll
            for (int j = 0; j < 8; j++) fma2(acc[j], vv, kp[j]);
        }
    }

    float* kvo = KV + ((size_t)nh * HD + m) * HD + d0;
    #pragma unroll
    for (int j = 0; j < 8; j++) {
        float2 p = unpk(acc[j]);
        atomicAdd(kvo + 2 * j,     p.x);
        atomicAdd(kvo + 2 * j + 1, p.y);
    }
}

// ---------------- K_sum[d] = sum_s K[s][d] per (n,h) -----------------------
// grid (NH=64, 8 splits), 64 threads
__global__ void ksum_kernel(const float* __restrict__ Kl, float* __restrict__ KS)
{
    const int nh = blockIdx.x;
    const int n  = nh >> 4;
    const int h  = nh & 15;
    const int d  = threadIdx.x;
    const size_t base = ((size_t)n * SEQ + blockIdx.y * 512) * D_MODEL + h * HD + d;
    float s = 0.f;
    for (int i = 0; i < 512; i++) s += Kl[base + (size_t)i * D_MODEL];
    atomicAdd(&KS[nh * HD + d], s);
}

// ---------------- Out[l][m] = Z(l) * sum_d Q[l][d] * KV[m][d] per (n,h) ----
// grid (L/64 = 64 tiles, NH = 64), 256 threads. Thread tile: 4l x 4m.
__global__ __launch_bounds__(256)
void attn_out_kernel(const float* __restrict__ Ql, const float* __restrict__ KV,
                     const float* __restrict__ KS, float* __restrict__ Out)
{
    __shared__ float Qs[64][68];    // [l_local][d], padded
    __shared__ float KVT[64][66];   // [d][m], padded (even stride for ld.64)
    __shared__ float ks[64];
    __shared__ float zs[64];

    const int nh = blockIdx.y;
    const int n  = nh >> 4;
    const int h  = nh & 15;
    const int l0 = blockIdx.x * 64;
    const int t  = threadIdx.x;

    // load Q tile (64x64) as float4
    for (int i = t; i < 64 * 16; i += 256) {
        const int r  = i >> 4;
        const int c4 = i & 15;
        float4 v = *(const float4*)(Ql + (size_t)(n * SEQ + l0 + r) * D_MODEL
                                       + h * HD + c4 * 4);
        *(float4*)&Qs[r][c4 * 4] = v;
    }
    // load KV transposed into KVT[d][m]
    for (int i = t; i < 4096; i += 256) {
        const int m = i >> 6;
        const int d = i & 63;
        KVT[d][m] = KV[((size_t)nh * HD + m) * HD + d];
    }
    if (t < 64) ks[t] = KS[nh * HD + t];
    __syncthreads();

    // normalizer Z per row
    if (t < 64) {
        float a = 0.f;
        #pragma unroll 8
        for (int d = 0; d < 64; d++) a += Qs[t][d] * ks[d];
        zs[t] = 1.f / (a + 1e-10f);
    }
    __syncthreads();

    const int tl = t >> 4;           // 0..15 -> rows tl*4 .. tl*4+3
    const int tm = t & 15;           // cols tm*4 .. tm*4+3

    ull acc[4][2];
    #pragma unroll
    for (int i = 0; i < 4; i++) { acc[i][0] = 0ull; acc[i][1] = 0ull; }

    #pragma unroll 8
    for (int d = 0; d < 64; d++) {
        const ull kv0 = *(const ull*)&KVT[d][tm * 4];
        const ull kv1 = *(const ull*)&KVT[d][tm * 4 + 2];
        #pragma unroll
        for (int i = 0; i < 4; i++) {
            const ull qd = dup2(Qs[tl * 4 + i][d]);
            fma2(acc[i][0], qd, kv0);
            fma2(acc[i][1], qd, kv1);
        }
    }

    #pragma unroll
    for (int i = 0; i < 4; i++) {
        const int l  = l0 + tl * 4 + i;
        const float z = zs[tl * 4 + i];
        float2 p0 = unpk(acc[i][0]);
        float2 p1 = unpk(acc[i][1]);
        float4 o = make_float4(p0.x * z, p0.y * z, p1.x * z, p1.y * z);
        *(float4*)(Out + (size_t)(n * SEQ + l) * D_MODEL + h * HD + tm * 4) = o;
    }
}

// ---------------- launch ---------------------------------------------------
extern "C" void kernel_launch(void* const* d_in, const int* in_sizes, int n_in,
                              void* d_out, int out_size)
{
    const float* queries = (const float*)d_in[0];
    const float* keys    = (const float*)d_in[1];
    const float* values  = (const float*)d_in[2];
    const float* Wq = (const float*)d_in[3];
    const float* bq = (const float*)d_in[4];
    const float* Wk = (const float*)d_in[5];
    const float* bk = (const float*)d_in[6];
    const float* Wv = (const float*)d_in[7];
    const float* bv = (const float*)d_in[8];
    const float* Wo = (const float*)d_in[9];
    const float* bo = (const float*)d_in[10];
    float* out = (float*)d_out;

    void *pQ, *pK, *pV, *pVL, *pKV, *pKS;
    cudaGetSymbolAddress(&pQ,  g_Q);
    cudaGetSymbolAddress(&pK,  g_K);
    cudaGetSymbolAddress(&pV,  g_V);
    cudaGetSymbolAddress(&pVL, g_VL);
    cudaGetSymbolAddress(&pKV, g_KV);
    cudaGetSymbolAddress(&pKS, g_KS);

    // zero the accumulation scratch
    zero_kernel<<<(NH * HD * HD + 255) / 256, 256>>>((float*)pKV, NH * HD * HD);
    zero_kernel<<<(NH * HD + 255) / 256, 256>>>((float*)pKS, NH * HD);

    dim3 gg(D_MODEL / GBN, M_TOTAL / GBM);   // (8, 128)

    // projections (elu+1 fused for Q and K)
    gemm_bias_act<<<gg, 256>>>(queries, Wq, bq, (float*)pQ, M_TOTAL, D_MODEL, D_MODEL, 1);
    gemm_bias_act<<<gg, 256>>>(keys,    Wk, bk, (float*)pK, M_TOTAL, D_MODEL, D_MODEL, 1);
    gemm_bias_act<<<gg, 256>>>(values,  Wv, bv, (float*)pV, M_TOTAL, D_MODEL, D_MODEL, 0);

    // linear attention core
    kv_kernel<<<dim3(NH, 8), 256>>>((const float*)pK, (const float*)pV, (float*)pKV);
    ksum_kernel<<<dim3(NH, 8), 64>>>((const float*)pK, (float*)pKS);
    attn_out_kernel<<<dim3(SEQ / 64, NH), 256>>>((const float*)pQ, (const float*)pKV,
                                                 (const float*)pKS, (float*)pVL);

    // output projection
    gemm_bias_act<<<gg, 256>>>((const float*)pVL, Wo, bo, out, M_TOTAL, D_MODEL, D_MODEL, 0);
}

// round 5
// speedup vs baseline: 1.8953x; 1.8953x over previous
#include <cuda_runtime.h>
#include <cuda_bf16.h>
#include <math.h>
#include <cstdint>

// Problem constants
#define D_MODEL 1024
#define N_BATCH 4
#define SEQ     4096
#define HEADS   16
#define HD      64
#define NH      (N_BATCH * HEADS)        // 64
#define M_TOTAL (N_BATCH * SEQ)          // 16384

typedef unsigned long long ull;
typedef __nv_bfloat16 bf;

// ---------------- scratch (device globals: no allocation allowed) ----------
__device__ float g_Q [M_TOTAL * D_MODEL];   // Q_lin  (elu+1 applied)
__device__ float g_K [M_TOTAL * D_MODEL];   // K_lin  (elu+1 applied)
__device__ float g_V [M_TOTAL * D_MODEL];   // V projection
__device__ float g_VL[M_TOTAL * D_MODEL];   // attention output (pre-Wo)
__device__ float g_KV[NH * HD * HD];        // per-(n,h) KV[m][d]
__device__ float g_KS[NH * HD];             // per-(n,h) K_sum[d]

// bf16 split scratch for tensor-core GEMMs
__device__ bf g_Ah[M_TOTAL * D_MODEL];
__device__ bf g_Al[M_TOTAL * D_MODEL];
__device__ bf g_Wqh[D_MODEL * D_MODEL], g_Wql[D_MODEL * D_MODEL];
__device__ bf g_Wkh[D_MODEL * D_MODEL], g_Wkl[D_MODEL * D_MODEL];
__device__ bf g_Wvh[D_MODEL * D_MODEL], g_Wvl[D_MODEL * D_MODEL];
__device__ bf g_Woh[D_MODEL * D_MODEL], g_Wol[D_MODEL * D_MODEL];

// ---------------- ptx helpers ---------------------------------------------
__device__ __forceinline__ uint32_t smem_u32(const void* p) {
    uint32_t a;
    asm("{ .reg .u64 t; cvta.to.shared.u64 t, %1; cvt.u32.u64 %0, t; }" : "=r"(a) : "l"(p));
    return a;
}
__device__ __forceinline__ void cp_async16(uint32_t s, const void* g) {
    asm volatile("cp.async.cg.shared.global [%0], [%1], 16;" :: "r"(s), "l"(g));
}
__device__ __forceinline__ void cpa_commit() { asm volatile("cp.async.commit_group;" ::: "memory"); }
__device__ __forceinline__ void cpa_wait2()  { asm volatile("cp.async.wait_group 2;" ::: "memory"); }

#define LDSM4(r, a) \
    asm volatile("ldmatrix.sync.aligned.m8n8.x4.shared.b16 {%0,%1,%2,%3}, [%4];" \
        : "=r"((r)[0]), "=r"((r)[1]), "=r"((r)[2]), "=r"((r)[3]) : "r"(a))

#define MMA16816(d, a, b) \
    asm volatile("mma.sync.aligned.m16n8k16.row.col.f32.bf16.bf16.f32 " \
        "{%0,%1,%2,%3}, {%4,%5,%6,%7}, {%8,%9}, {%0,%1,%2,%3};" \
        : "+f"((d)[0]), "+f"((d)[1]), "+f"((d)[2]), "+f"((d)[3]) \
        : "r"((a)[0]), "r"((a)[1]), "r"((a)[2]), "r"((a)[3]), \
          "r"((b)[0]), "r"((b)[1]))

// ---------------- packed f32x2 helpers (attention core) --------------------
__device__ __forceinline__ void fma2(ull& d, ull a, ull b) {
    asm("fma.rn.f32x2 %0, %1, %2, %3;" : "=l"(d) : "l"(a), "l"(b), "l"(d));
}
__device__ __forceinline__ ull dup2(float x) {
    ull r; asm("mov.b64 %0, {%1, %1};" : "=l"(r) : "f"(x)); return r;
}
__device__ __forceinline__ float2 unpk(ull a) {
    float2 r; asm("mov.b64 {%0, %1}, %2;" : "=f"(r.x), "=f"(r.y) : "l"(a));
    return r;
}

// ================= mma.sync GEMM: C[M,1024] = A[M,1024]*W + bias (+elu+1) ==
// A as bf16 hi/lo [M,K] row-major; W as transposed bf16 hi/lo [N,K] row-major.
// Tile: BM=128, BN=128, BK=32, 4-stage cp.async pipeline, 8 warps (2x4).
// bf16x3: C = AhBh + AhBl + AlBh, fp32 accumulators.
// Smem rows: 32 bf16 + 8 pad = 80B stride (5x16B, coprime 8 -> ldmatrix
// conflict-free without explicit swizzle).

#define T_ROWB   80
#define T_BYTES  (128 * T_ROWB)          // 10240
#define ST_BYTES (4 * T_BYTES)           // 40960
#define OFF_AH   0
#define OFF_AL   T_BYTES
#define OFF_BH   (2 * T_BYTES)
#define OFF_BL   (3 * T_BYTES)
#define GSTAGES  4
#define SM_BIAS  (GSTAGES * ST_BYTES)    // 163840
#define SM_TOTAL (SM_BIAS + 512)
#define NCHUNK   (D_MODEL / 32)          // 32

__device__ __forceinline__ void load_stage(
    uint32_t sb, const bf* __restrict__ Ah, const bf* __restrict__ Al,
    const bf* __restrict__ Bh, const bf* __restrict__ Bl,
    int brow0, int bcol0, int kt, int tid)
{
    const uint32_t st = sb + (uint32_t)(kt & (GSTAGES - 1)) * ST_BYTES;
    const size_t kof = (size_t)kt * 32;
    #pragma unroll
    for (int v = 0; v < 2; v++) {
        const int idx = v * 256 + tid;
        const int r  = idx >> 2;
        const int cc = idx & 3;
        const uint32_t so = (uint32_t)(r * T_ROWB + cc * 16);
        const size_t gA = (size_t)(brow0 + r) * D_MODEL + kof + cc * 8;
        const size_t gB = (size_t)(bcol0 + r) * D_MODEL + kof + cc * 8;
        cp_async16(st + OFF_AH + so, Ah + gA);
        cp_async16(st + OFF_AL + so, Al + gA);
        cp_async16(st + OFF_BH + so, Bh + gB);
        cp_async16(st + OFF_BL + so, Bl + gB);
    }
}

__global__ __launch_bounds__(256, 1)
void gemm_tc(const bf* __restrict__ Ah, const bf* __restrict__ Al,
             const bf* __restrict__ Bh, const bf* __restrict__ Bl,
             const float* __restrict__ bias, float* __restrict__ C, int act)
{
    extern __shared__ char smem[];
    const uint32_t sb = smem_u32(smem);
    const int tid  = threadIdx.x;
    const int lane = tid & 31;
    const int w    = tid >> 5;
    const int wm   = w >> 2;         // 0..1  (m direction, 64 rows each)
    const int wn   = w & 3;          // 0..3  (n direction, 32 cols each)
    const int brow0 = blockIdx.y * 128;
    const int bcol0 = blockIdx.x * 128;

    if (tid < 128) ((float*)(smem + SM_BIAS))[tid] = bias[bcol0 + tid];

    float c[4][4][4];
    #pragma unroll
    for (int mi = 0; mi < 4; mi++)
        #pragma unroll
        for (int ni = 0; ni < 4; ni++)
            #pragma unroll
            for (int q = 0; q < 4; q++) c[mi][ni][q] = 0.f;

    // prologue: stages 0..2
    #pragma unroll
    for (int s = 0; s < GSTAGES - 1; s++) {
        load_stage(sb, Ah, Al, Bh, Bl, brow0, bcol0, s, tid);
        cpa_commit();
    }

    // precomputed ldmatrix lane offsets
    const uint32_t a_lrow = (uint32_t)((lane & 15) * T_ROWB + ((lane >> 4) << 4));
    const uint32_t b_lrow = (uint32_t)(((((lane >> 4) & 1) * 8 + (lane & 7)) * T_ROWB)
                                       + (((lane >> 3) & 1) << 4));

    for (int kt = 0; kt < NCHUNK; kt++) {
        cpa_wait2();                 // chunk kt resident
        __syncthreads();             // visible to all warps; frees buf (kt-1)%4
        if (kt + GSTAGES - 1 < NCHUNK)
            load_stage(sb, Ah, Al, Bh, Bl, brow0, bcol0, kt + GSTAGES - 1, tid);
        cpa_commit();

        const uint32_t st = sb + (uint32_t)(kt & (GSTAGES - 1)) * ST_BYTES;

        #pragma unroll
        for (int ks = 0; ks < 2; ks++) {
            const uint32_t kb = ks * 32;   // byte offset of k16 step

            uint32_t ah[4][4], al_[4][4];
            #pragma unroll
            for (int mi = 0; mi < 4; mi++) {
                const uint32_t ra = st + OFF_AH
                    + (uint32_t)((wm * 64 + mi * 16) * T_ROWB) + a_lrow + kb;
                LDSM4(ah[mi], ra);
                LDSM4(al_[mi], ra + (OFF_AL - OFF_AH));
            }
            uint32_t bh[4][2], bl_[4][2];
            #pragma unroll
            for (int bi = 0; bi < 2; bi++) {
                const uint32_t rb = st + OFF_BH
                    + (uint32_t)((wn * 32 + bi * 16) * T_ROWB) + b_lrow + kb;
                uint32_t t4[4];
                LDSM4(t4, rb);
                bh[2 * bi][0] = t4[0]; bh[2 * bi][1] = t4[1];
                bh[2 * bi + 1][0] = t4[2]; bh[2 * bi + 1][1] = t4[3];
                LDSM4(t4, rb + (OFF_BL - OFF_BH));
                bl_[2 * bi][0] = t4[0]; bl_[2 * bi][1] = t4[1];
                bl_[2 * bi + 1][0] = t4[2]; bl_[2 * bi + 1][1] = t4[3];
            }
            #pragma unroll
            for (int mi = 0; mi < 4; mi++)
                #pragma unroll
                for (int ni = 0; ni < 4; ni++) {
                    MMA16816(c[mi][ni], ah[mi],  bh[ni]);
                    MMA16816(c[mi][ni], ah[mi],  bl_[ni]);
                    MMA16816(c[mi][ni], al_[mi], bh[ni]);
                }
        }
    }

    // epilogue
    const float* sbias = (const float*)(smem + SM_BIAS);
    const int r0 = lane >> 2;
    const int c0 = (lane & 3) * 2;
    #pragma unroll
    for (int mi = 0; mi < 4; mi++) {
        const int m = brow0 + wm * 64 + mi * 16 + r0;
        #pragma unroll
        for (int ni = 0; ni < 4; ni++) {
            const int n = wn * 32 + ni * 8 + c0;
            const float b0 = sbias[n], b1 = sbias[n + 1];
            float v0 = c[mi][ni][0] + b0;
            float v1 = c[mi][ni][1] + b1;
            float v2 = c[mi][ni][2] + b0;
            float v3 = c[mi][ni][3] + b1;
            if (act) {
                v0 = (v0 > 0.f) ? (v0 + 1.f) : expf(v0);
                v1 = (v1 > 0.f) ? (v1 + 1.f) : expf(v1);
                v2 = (v2 > 0.f) ? (v2 + 1.f) : expf(v2);
                v3 = (v3 > 0.f) ? (v3 + 1.f) : expf(v3);
            }
            *(float2*)(C + (size_t)m * D_MODEL + bcol0 + n)       = make_float2(v0, v1);
            *(float2*)(C + (size_t)(m + 8) * D_MODEL + bcol0 + n) = make_float2(v2, v3);
        }
    }
}

// ---------------- fp32 -> bf16 hi/lo split (elementwise) -------------------
__global__ void convert_a_kernel(const float* __restrict__ X,
                                 bf* __restrict__ H, bf* __restrict__ L, int n4)
{
    int i = blockIdx.x * blockDim.x + threadIdx.x;
    if (i >= n4) return;
    float4 x = ((const float4*)X)[i];
    bf h0 = __float2bfloat16_rn(x.x);
    bf h1 = __float2bfloat16_rn(x.y);
    bf h2 = __float2bfloat16_rn(x.z);
    bf h3 = __float2bfloat16_rn(x.w);
    bf l0 = __float2bfloat16_rn(x.x - __bfloat162float(h0));
    bf l1 = __float2bfloat16_rn(x.y - __bfloat162float(h1));
    bf l2 = __float2bfloat16_rn(x.z - __bfloat162float(h2));
    bf l3 = __float2bfloat16_rn(x.w - __bfloat162float(h3));
    __nv_bfloat162 ph0; ph0.x = h0; ph0.y = h1;
    __nv_bfloat162 ph1; ph1.x = h2; ph1.y = h3;
    __nv_bfloat162 pl0; pl0.x = l0; pl0.y = l1;
    __nv_bfloat162 pl1; pl1.x = l2; pl1.y = l3;
    ((__nv_bfloat162*)H)[2 * i]     = ph0;
    ((__nv_bfloat162*)H)[2 * i + 1] = ph1;
    ((__nv_bfloat162*)L)[2 * i]     = pl0;
    ((__nv_bfloat162*)L)[2 * i + 1] = pl1;
}

// ---------------- weight transpose + split: W[K,N] -> WT[N,K] hi/lo --------
__global__ void convert_w_kernel(const float* __restrict__ W,
                                 bf* __restrict__ TH, bf* __restrict__ TL)
{
    __shared__ float t[32][33];
    const int bn = blockIdx.x * 32;
    const int bk = blockIdx.y * 32;
    const int tx = threadIdx.x, ty = threadIdx.y;   // (32, 8)
    #pragma unroll
    for (int j = 0; j < 32; j += 8)
        t[ty + j][tx] = W[(size_t)(bk + ty + j) * D_MODEL + bn + tx];
    __syncthreads();
    #pragma unroll
    for (int j = 0; j < 32; j += 8) {
        const float v = t[tx][ty + j];
        const bf h = __float2bfloat16_rn(v);
        const bf l = __float2bfloat16_rn(v - __bfloat162float(h));
        const size_t o = (size_t)(bn + ty + j) * D_MODEL + bk + tx;
        TH[o] = h;
        TL[o] = l;
    }
}

// ---------------- zero scratch -------------------------------------------
__global__ void zero_kernel(float* p, int n)
{
    int i = blockIdx.x * blockDim.x + threadIdx.x;
    if (i < n) p[i] = 0.f;
}

// ---------------- KV[m][d] = sum_s K[s][d] * V[s][m] per (n,h) -------------
__global__ void kv_kernel(const float* __restrict__ Kl, const float* __restrict__ Vb,
                          float* __restrict__ KV)
{
    __shared__ float Ks[8][64];
    __shared__ float Vs[8][64];

    const int nh = blockIdx.x;
    const int n  = nh >> 4;
    const int h  = nh & 15;
    const int t  = threadIdx.x;
    const int m  = t >> 2;
    const int d0 = (t & 3) << 4;

    const size_t base = (size_t)n * SEQ * D_MODEL + (size_t)h * HD;
    const int s0 = blockIdx.y * 512;

    const int lr = t >> 5;
    const int lc = (t & 31) * 2;

    ull acc[8];
    #pragma unroll
    for (int j = 0; j < 8; j++) acc[j] = 0ull;

    for (int s = s0; s < s0 + 512; s += 8) {
        const float2 kx = *(const float2*)(Kl + base + (size_t)(s + lr) * D_MODEL + lc);
        const float2 vx = *(const float2*)(Vb + base + (size_t)(s + lr) * D_MODEL + lc);
        __syncthreads();
        *(float2*)&Ks[lr][lc] = kx;
        *(float2*)&Vs[lr][lc] = vx;
        __syncthreads();
        #pragma unroll
        for (int ss = 0; ss < 8; ss++) {
            const ull vv = dup2(Vs[ss][m]);
            const ull* kp = (const ull*)&Ks[ss][d0];
            #pragma unroll
            for (int j = 0; j < 8; j++) fma2(acc[j], vv, kp[j]);
        }
    }

    float* kvo = KV + ((size_t)nh * HD + m) * HD + d0;
    #pragma unroll
    for (int j = 0; j < 8; j++) {
        float2 p = unpk(acc[j]);
        atomicAdd(kvo + 2 * j,     p.x);
        atomicAdd(kvo + 2 * j + 1, p.y);
    }
}

// ---------------- K_sum[d] = sum_s K[s][d] per (n,h) -----------------------
__global__ void ksum_kernel(const float* __restrict__ Kl, float* __restrict__ KS)
{
    const int nh = blockIdx.x;
    const int n  = nh >> 4;
    const int h  = nh & 15;
    const int d  = threadIdx.x;
    const size_t base = ((size_t)n * SEQ + blockIdx.y * 512) * D_MODEL + h * HD + d;
    float s = 0.f;
    for (int i = 0; i < 512; i++) s += Kl[base + (size_t)i * D_MODEL];
    atomicAdd(&KS[nh * HD + d], s);
}

// ---------------- Out[l][m] = Z(l) * sum_d Q[l][d] * KV[m][d] per (n,h) ----
__global__ __launch_bounds__(256)
void attn_out_kernel(const float* __restrict__ Ql, const float* __restrict__ KV,
                     const float* __restrict__ KS, float* __restrict__ Out)
{
    __shared__ float Qs[64][68];
    __shared__ float KVT[64][66];
    __shared__ float ks[64];
    __shared__ float zs[64];

    const int nh = blockIdx.y;
    const int n  = nh >> 4;
    const int h  = nh & 15;
    const int l0 = blockIdx.x * 64;
    const int t  = threadIdx.x;

    for (int i = t; i < 64 * 16; i += 256) {
        const int r  = i >> 4;
        const int c4 = i & 15;
        float4 v = *(const float4*)(Ql + (size_t)(n * SEQ + l0 + r) * D_MODEL
                                       + h * HD + c4 * 4);
        *(float4*)&Qs[r][c4 * 4] = v;
    }
    for (int i = t; i < 4096; i += 256) {
        const int m = i >> 6;
        const int d = i & 63;
        KVT[d][m] = KV[((size_t)nh * HD + m) * HD + d];
    }
    if (t < 64) ks[t] = KS[nh * HD + t];
    __syncthreads();

    if (t < 64) {
        float a = 0.f;
        #pragma unroll 8
        for (int d = 0; d < 64; d++) a += Qs[t][d] * ks[d];
        zs[t] = 1.f / (a + 1e-10f);
    }
    __syncthreads();

    const int tl = t >> 4;
    const int tm = t & 15;

    ull acc[4][2];
    #pragma unroll
    for (int i = 0; i < 4; i++) { acc[i][0] = 0ull; acc[i][1] = 0ull; }

    #pragma unroll 8
    for (int d = 0; d < 64; d++) {
        const ull kv0 = *(const ull*)&KVT[d][tm * 4];
        const ull kv1 = *(const ull*)&KVT[d][tm * 4 + 2];
        #pragma unroll
        for (int i = 0; i < 4; i++) {
            const ull qd = dup2(Qs[tl * 4 + i][d]);
            fma2(acc[i][0], qd, kv0);
            fma2(acc[i][1], qd, kv1);
        }
    }

    #pragma unroll
    for (int i = 0; i < 4; i++) {
        const int l  = l0 + tl * 4 + i;
        const float z = zs[tl * 4 + i];
        float2 p0 = unpk(acc[i][0]);
        float2 p1 = unpk(acc[i][1]);
        float4 o = make_float4(p0.x * z, p0.y * z, p1.x * z, p1.y * z);
        *(float4*)(Out + (size_t)(n * SEQ + l) * D_MODEL + h * HD + tm * 4) = o;
    }
}

// ---------------- launch ---------------------------------------------------
extern "C" void kernel_launch(void* const* d_in, const int* in_sizes, int n_in,
                              void* d_out, int out_size)
{
    const float* queries = (const float*)d_in[0];
    const float* keys    = (const float*)d_in[1];
    const float* values  = (const float*)d_in[2];
    const float* Wq = (const float*)d_in[3];
    const float* bq = (const float*)d_in[4];
    const float* Wk = (const float*)d_in[5];
    const float* bk = (const float*)d_in[6];
    const float* Wv = (const float*)d_in[7];
    const float* bv = (const float*)d_in[8];
    const float* Wo = (const float*)d_in[9];
    const float* bo = (const float*)d_in[10];
    float* out = (float*)d_out;

    void *pQ, *pK, *pV, *pVL, *pKV, *pKS, *pAh, *pAl;
    void *pWqh, *pWql, *pWkh, *pWkl, *pWvh, *pWvl, *pWoh, *pWol;
    cudaGetSymbolAddress(&pQ,  g_Q);
    cudaGetSymbolAddress(&pK,  g_K);
    cudaGetSymbolAddress(&pV,  g_V);
    cudaGetSymbolAddress(&pVL, g_VL);
    cudaGetSymbolAddress(&pKV, g_KV);
    cudaGetSymbolAddress(&pKS, g_KS);
    cudaGetSymbolAddress(&pAh, g_Ah);
    cudaGetSymbolAddress(&pAl, g_Al);
    cudaGetSymbolAddress(&pWqh, g_Wqh); cudaGetSymbolAddress(&pWql, g_Wql);
    cudaGetSymbolAddress(&pWkh, g_Wkh); cudaGetSymbolAddress(&pWkl, g_Wkl);
    cudaGetSymbolAddress(&pWvh, g_Wvh); cudaGetSymbolAddress(&pWvl, g_Wvl);
    cudaGetSymbolAddress(&pWoh, g_Woh); cudaGetSymbolAddress(&pWol, g_Wol);

    cudaFuncSetAttribute(gemm_tc, cudaFuncAttributeMaxDynamicSharedMemorySize, SM_TOTAL);

    const int n4 = M_TOTAL * D_MODEL / 4;
    dim3 cw_grid(32, 32), cw_blk(32, 8);
    dim3 gg(D_MODEL / 128, M_TOTAL / 128);    // (8, 128)

    // weight transpose + split
    convert_w_kernel<<<cw_grid, cw_blk>>>(Wq, (bf*)pWqh, (bf*)pWql);
    convert_w_kernel<<<cw_grid, cw_blk>>>(Wk, (bf*)pWkh, (bf*)pWkl);
    convert_w_kernel<<<cw_grid, cw_blk>>>(Wv, (bf*)pWvh, (bf*)pWvl);
    convert_w_kernel<<<cw_grid, cw_blk>>>(Wo, (bf*)pWoh, (bf*)pWol);

    // zero attention accumulators
    zero_kernel<<<(NH * HD * HD + 255) / 256, 256>>>((float*)pKV, NH * HD * HD);
    zero_kernel<<<(NH * HD + 255) / 256, 256>>>((float*)pKS, NH * HD);

    // Q projection (elu+1)
    convert_a_kernel<<<(n4 + 255) / 256, 256>>>(queries, (bf*)pAh, (bf*)pAl, n4);
    gemm_tc<<<gg, 256, SM_TOTAL>>>((bf*)pAh, (bf*)pAl, (bf*)pWqh, (bf*)pWql,
                                   bq, (float*)pQ, 1);
    // K projection (elu+1)
    convert_a_kernel<<<(n4 + 255) / 256, 256>>>(keys, (bf*)pAh, (bf*)pAl, n4);
    gemm_tc<<<gg, 256, SM_TOTAL>>>((bf*)pAh, (bf*)pAl, (bf*)pWkh, (bf*)pWkl,
                                   bk, (float*)pK, 1);
    // V projection
    convert_a_kernel<<<(n4 + 255) / 256, 256>>>(values, (bf*)pAh, (bf*)pAl, n4);
    gemm_tc<<<gg, 256, SM_TOTAL>>>((bf*)pAh, (bf*)pAl, (bf*)pWvh, (bf*)pWvl,
                                   bv, (float*)pV, 0);

    // linear attention core
    kv_kernel<<<dim3(NH, 8), 256>>>((const float*)pK, (const float*)pV, (float*)pKV);
    ksum_kernel<<<dim3(NH, 8), 64>>>((const float*)pK, (float*)pKS);
    attn_out_kernel<<<dim3(SEQ / 64, NH), 256>>>((const float*)pQ, (const float*)pKV,
                                                 (const float*)pKS, (float*)pVL);

    // output projection
    convert_a_kernel<<<(n4 + 255) / 256, 256>>>((const float*)pVL, (bf*)pAh, (bf*)pAl, n4);
    gemm_tc<<<gg, 256, SM_TOTAL>>>((bf*)pAh, (bf*)pAl, (bf*)pWoh, (bf*)pWol,
                                   bo, out, 0);
}

// round 6
// speedup vs baseline: 2.6771x; 1.4125x over previous
#include <cuda_runtime.h>
#include <cuda_fp16.h>
#include <math.h>
#include <cstdint>

// Problem constants
#define D_MODEL 1024
#define N_BATCH 4
#define SEQ     4096
#define HEADS   16
#define HD      64
#define NH      (N_BATCH * HEADS)        // 64
#define M_TOTAL (N_BATCH * SEQ)          // 16384

typedef unsigned long long ull;
typedef __half hf;

// ---------------- scratch (device globals: no allocation allowed) ----------
__device__ float g_Q [M_TOTAL * D_MODEL];   // Q_lin  (elu+1 applied)
__device__ float g_K [M_TOTAL * D_MODEL];   // K_lin  (elu+1 applied)
__device__ float g_V [M_TOTAL * D_MODEL];   // V projection
__device__ float g_KV[NH * HD * HD];        // per-(n,h) KV[m][d]
__device__ float g_KS[NH * HD];             // per-(n,h) K_sum[d]

// fp16 scratch for tensor-core GEMMs (A single-rounded, W hi/lo split)
__device__ hf g_Ah[M_TOTAL * D_MODEL];
__device__ hf g_Wqh[D_MODEL * D_MODEL], g_Wql[D_MODEL * D_MODEL];
__device__ hf g_Wkh[D_MODEL * D_MODEL], g_Wkl[D_MODEL * D_MODEL];
__device__ hf g_Wvh[D_MODEL * D_MODEL], g_Wvl[D_MODEL * D_MODEL];
__device__ hf g_Woh[D_MODEL * D_MODEL], g_Wol[D_MODEL * D_MODEL];

// ---------------- ptx helpers ---------------------------------------------
__device__ __forceinline__ uint32_t smem_u32(const void* p) {
    uint32_t a;
    asm("{ .reg .u64 t; cvta.to.shared.u64 t, %1; cvt.u32.u64 %0, t; }" : "=r"(a) : "l"(p));
    return a;
}
__device__ __forceinline__ void cp_async16(uint32_t s, const void* g) {
    asm volatile("cp.async.cg.shared.global [%0], [%1], 16;" :: "r"(s), "l"(g));
}
__device__ __forceinline__ void cpa_commit() { asm volatile("cp.async.commit_group;" ::: "memory"); }
__device__ __forceinline__ void cpa_wait1()  { asm volatile("cp.async.wait_group 1;" ::: "memory"); }

#define LDSM4(r, a) \
    asm volatile("ldmatrix.sync.aligned.m8n8.x4.shared.b16 {%0,%1,%2,%3}, [%4];" \
        : "=r"((r)[0]), "=r"((r)[1]), "=r"((r)[2]), "=r"((r)[3]) : "r"(a))

#define MMA16816(d, a, b) \
    asm volatile("mma.sync.aligned.m16n8k16.row.col.f32.f16.f16.f32 " \
        "{%0,%1,%2,%3}, {%4,%5,%6,%7}, {%8,%9}, {%0,%1,%2,%3};" \
        : "+f"((d)[0]), "+f"((d)[1]), "+f"((d)[2]), "+f"((d)[3]) \
        : "r"((a)[0]), "r"((a)[1]), "r"((a)[2]), "r"((a)[3]), \
          "r"((b)[0]), "r"((b)[1]))

// ---------------- packed f32x2 helpers (attention core) --------------------
__device__ __forceinline__ void fma2(ull& d, ull a, ull b) {
    asm("fma.rn.f32x2 %0, %1, %2, %3;" : "=l"(d) : "l"(a), "l"(b), "l"(d));
}
__device__ __forceinline__ ull dup2(float x) {
    ull r; asm("mov.b64 %0, {%1, %1};" : "=l"(r) : "f"(x)); return r;
}
__device__ __forceinline__ float2 unpk(ull a) {
    float2 r; asm("mov.b64 {%0, %1}, %2;" : "=f"(r.x), "=f"(r.y) : "l"(a));
    return r;
}

// ================= mma.sync GEMM: C[M,1024] = A[M,1024]*W + bias (+elu+1) ==
// A as fp16 [M,K] row-major; W as transposed fp16 hi/lo [N,K] row-major.
// Tile: BM=128, BN=128, BK=32, 3-stage cp.async pipeline, 8 warps (2x4),
// 2 CTAs/SM. fp16x2: C = Ah*Bh + Ah*Bl, fp32 accumulators.
// Smem rows: 32 fp16 + 8 pad = 80B stride (5x16B, coprime 8 -> ldmatrix
// conflict-free without explicit swizzle).

#define T_ROWB   80
#define T_BYTES  (128 * T_ROWB)          // 10240
#define ST_BYTES (3 * T_BYTES)           // 30720 (Ah, Bh, Bl)
#define OFF_AH   0
#define OFF_BH   T_BYTES
#define OFF_BL   (2 * T_BYTES)
#define GSTAGES  3
#define SM_BIAS  (GSTAGES * ST_BYTES)    // 92160
#define SM_TOTAL (SM_BIAS + 512)
#define NCHUNK   (D_MODEL / 32)          // 32

__device__ __forceinline__ void load_stage(
    uint32_t sb, const hf* __restrict__ Ah,
    const hf* __restrict__ Bh, const hf* __restrict__ Bl,
    int brow0, int bcol0, int kt, int tid)
{
    const uint32_t st = sb + (uint32_t)(kt % GSTAGES) * ST_BYTES;
    const size_t kof = (size_t)kt * 32;
    #pragma unroll
    for (int v = 0; v < 2; v++) {
        const int idx = v * 256 + tid;
        const int r  = idx >> 2;
        const int cc = idx & 3;
        const uint32_t so = (uint32_t)(r * T_ROWB + cc * 16);
        const size_t gA = (size_t)(brow0 + r) * D_MODEL + kof + cc * 8;
        const size_t gB = (size_t)(bcol0 + r) * D_MODEL + kof + cc * 8;
        cp_async16(st + OFF_AH + so, Ah + gA);
        cp_async16(st + OFF_BH + so, Bh + gB);
        cp_async16(st + OFF_BL + so, Bl + gB);
    }
}

__global__ __launch_bounds__(256, 2)
void gemm_tc(const hf* __restrict__ Ah,
             const hf* __restrict__ Bh, const hf* __restrict__ Bl,
             const float* __restrict__ bias, float* __restrict__ C, int act)
{
    extern __shared__ char smem[];
    const uint32_t sb = smem_u32(smem);
    const int tid  = threadIdx.x;
    const int lane = tid & 31;
    const int w    = tid >> 5;
    const int wm   = w >> 2;         // 0..1  (m direction, 64 rows each)
    const int wn   = w & 3;          // 0..3  (n direction, 32 cols each)
    const int brow0 = blockIdx.y * 128;
    const int bcol0 = blockIdx.x * 128;

    if (tid < 128) ((float*)(smem + SM_BIAS))[tid] = bias[bcol0 + tid];

    float c[4][4][4];
    #pragma unroll
    for (int mi = 0; mi < 4; mi++)
        #pragma unroll
        for (int ni = 0; ni < 4; ni++)
            #pragma unroll
            for (int q = 0; q < 4; q++) c[mi][ni][q] = 0.f;

    // prologue: stages 0..1
    #pragma unroll
    for (int s = 0; s < GSTAGES - 1; s++) {
        load_stage(sb, Ah, Bh, Bl, brow0, bcol0, s, tid);
        cpa_commit();
    }

    // precomputed ldmatrix lane offsets (validated in R5)
    const uint32_t a_lrow = (uint32_t)((lane & 15) * T_ROWB + ((lane >> 4) << 4));
    const uint32_t b_lrow = (uint32_t)(((((lane >> 4) & 1) * 8 + (lane & 7)) * T_ROWB)
                                       + (((lane >> 3) & 1) << 4));

    for (int kt = 0; kt < NCHUNK; kt++) {
        cpa_wait1();                 // group kt complete (empty-commit counting)
        __syncthreads();
        if (kt + GSTAGES - 1 < NCHUNK)
            load_stage(sb, Ah, Bh, Bl, brow0, bcol0, kt + GSTAGES - 1, tid);
        cpa_commit();                // unconditional: keeps group indexing exact

        const uint32_t st = sb + (uint32_t)(kt % GSTAGES) * ST_BYTES;

        #pragma unroll
        for (int ks = 0; ks < 2; ks++) {
            const uint32_t kb = ks * 32;   // byte offset of k16 step

            uint32_t ah[4][4];
            #pragma unroll
            for (int mi = 0; mi < 4; mi++) {
                const uint32_t ra = st + OFF_AH
                    + (uint32_t)((wm * 64 + mi * 16) * T_ROWB) + a_lrow + kb;
                LDSM4(ah[mi], ra);
            }
            uint32_t bh[4][2], bl_[4][2];
            #pragma unroll
            for (int bi = 0; bi < 2; bi++) {
                const uint32_t rb = st + OFF_BH
                    + (uint32_t)((wn * 32 + bi * 16) * T_ROWB) + b_lrow + kb;
                uint32_t t4[4];
                LDSM4(t4, rb);
                bh[2 * bi][0] = t4[0]; bh[2 * bi][1] = t4[1];
                bh[2 * bi + 1][0] = t4[2]; bh[2 * bi + 1][1] = t4[3];
                LDSM4(t4, rb + (OFF_BL - OFF_BH));
                bl_[2 * bi][0] = t4[0]; bl_[2 * bi][1] = t4[1];
                bl_[2 * bi + 1][0] = t4[2]; bl_[2 * bi + 1][1] = t4[3];
            }
            #pragma unroll
            for (int mi = 0; mi < 4; mi++)
                #pragma unroll
                for (int ni = 0; ni < 4; ni++) {
                    MMA16816(c[mi][ni], ah[mi], bh[ni]);
                    MMA16816(c[mi][ni], ah[mi], bl_[ni]);
                }
        }
    }

    // epilogue
    const float* sbias = (const float*)(smem + SM_BIAS);
    const int r0 = lane >> 2;
    const int c0 = (lane & 3) * 2;
    #pragma unroll
    for (int mi = 0; mi < 4; mi++) {
        const int m = brow0 + wm * 64 + mi * 16 + r0;
        #pragma unroll
        for (int ni = 0; ni < 4; ni++) {
            const int n = wn * 32 + ni * 8 + c0;
            const float b0 = sbias[n], b1 = sbias[n + 1];
            float v0 = c[mi][ni][0] + b0;
            float v1 = c[mi][ni][1] + b1;
            float v2 = c[mi][ni][2] + b0;
            float v3 = c[mi][ni][3] + b1;
            if (act) {
                v0 = (v0 > 0.f) ? (v0 + 1.f) : expf(v0);
                v1 = (v1 > 0.f) ? (v1 + 1.f) : expf(v1);
                v2 = (v2 > 0.f) ? (v2 + 1.f) : expf(v2);
                v3 = (v3 > 0.f) ? (v3 + 1.f) : expf(v3);
            }
            *(float2*)(C + (size_t)m * D_MODEL + bcol0 + n)       = make_float2(v0, v1);
            *(float2*)(C + (size_t)(m + 8) * D_MODEL + bcol0 + n) = make_float2(v2, v3);
        }
    }
}

// ---------------- fp32 -> fp16 (elementwise, for A operands) ---------------
__global__ void convert_a_kernel(const float* __restrict__ X,
                                 hf* __restrict__ H, int n4)
{
    int i = blockIdx.x * blockDim.x + threadIdx.x;
    if (i >= n4) return;
    float4 x = ((const float4*)X)[i];
    __half2 h0 = __floats2half2_rn(x.x, x.y);
    __half2 h1 = __floats2half2_rn(x.z, x.w);
    ((__half2*)H)[2 * i]     = h0;
    ((__half2*)H)[2 * i + 1] = h1;
}

// ---------------- weight transpose + split: W[K,N] -> WT[N,K] hi/lo --------
__global__ void convert_w_kernel(const float* __restrict__ W,
                                 hf* __restrict__ TH, hf* __restrict__ TL)
{
    __shared__ float t[32][33];
    const int bn = blockIdx.x * 32;
    const int bk = blockIdx.y * 32;
    const int tx = threadIdx.x, ty = threadIdx.y;   // (32, 8)
    #pragma unroll
    for (int j = 0; j < 32; j += 8)
        t[ty + j][tx] = W[(size_t)(bk + ty + j) * D_MODEL + bn + tx];
    __syncthreads();
    #pragma unroll
    for (int j = 0; j < 32; j += 8) {
        const float v = t[tx][ty + j];
        const hf h = __float2half_rn(v);
        const hf l = __float2half_rn(v - __half2float(h));
        const size_t o = (size_t)(bn + ty + j) * D_MODEL + bk + tx;
        TH[o] = h;
        TL[o] = l;
    }
}

// ---------------- zero scratch -------------------------------------------
__global__ void zero_kernel(float* p, int n)
{
    int i = blockIdx.x * blockDim.x + threadIdx.x;
    if (i < n) p[i] = 0.f;
}

// ---------------- KV[m][d] = sum_s K[s][d] * V[s][m] per (n,h) -------------
__global__ void kv_kernel(const float* __restrict__ Kl, const float* __restrict__ Vb,
                          float* __restrict__ KV)
{
    __shared__ float Ks[8][64];
    __shared__ float Vs[8][64];

    const int nh = blockIdx.x;
    const int n  = nh >> 4;
    const int h  = nh & 15;
    const int t  = threadIdx.x;
    const int m  = t >> 2;
    const int d0 = (t & 3) << 4;

    const size_t base = (size_t)n * SEQ * D_MODEL + (size_t)h * HD;
    const int s0 = blockIdx.y * 512;

    const int lr = t >> 5;
    const int lc = (t & 31) * 2;

    ull acc[8];
    #pragma unroll
    for (int j = 0; j < 8; j++) acc[j] = 0ull;

    for (int s = s0; s < s0 + 512; s += 8) {
        const float2 kx = *(const float2*)(Kl + base + (size_t)(s + lr) * D_MODEL + lc);
        const float2 vx = *(const float2*)(Vb + base + (size_t)(s + lr) * D_MODEL + lc);
        __syncthreads();
        *(float2*)&Ks[lr][lc] = kx;
        *(float2*)&Vs[lr][lc] = vx;
        __syncthreads();
        #pragma unroll
        for (int ss = 0; ss < 8; ss++) {
            const ull vv = dup2(Vs[ss][m]);
            const ull* kp = (const ull*)&Ks[ss][d0];
            #pragma unroll
            for (int j = 0; j < 8; j++) fma2(acc[j], vv, kp[j]);
        }
    }

    float* kvo = KV + ((size_t)nh * HD + m) * HD + d0;
    #pragma unroll
    for (int j = 0; j < 8; j++) {
        float2 p = unpk(acc[j]);
        atomicAdd(kvo + 2 * j,     p.x);
        atomicAdd(kvo + 2 * j + 1, p.y);
    }
}

// ---------------- K_sum[d] = sum_s K[s][d] per (n,h) -----------------------
__global__ void ksum_kernel(const float* __restrict__ Kl, float* __restrict__ KS)
{
    const int nh = blockIdx.x;
    const int n  = nh >> 4;
    const int h  = nh & 15;
    const int d  = threadIdx.x;
    const size_t base = ((size_t)n * SEQ + blockIdx.y * 512) * D_MODEL + h * HD + d;
    float s = 0.f;
    for (int i = 0; i < 512; i++) s += Kl[base + (size_t)i * D_MODEL];
    atomicAdd(&KS[nh * HD + d], s);
}

// ---------------- Out[l][m] = Z(l) * sum_d Q[l][d] * KV[m][d] per (n,h) ----
// Writes fp16 directly (becomes the A operand of the Wo GEMM).
__global__ __launch_bounds__(256)
void attn_out_kernel(const float* __restrict__ Ql, const float* __restrict__ KV,
                     const float* __restrict__ KS, hf* __restrict__ Out)
{
    __shared__ float Qs[64][68];
    __shared__ float KVT[64][66];
    __shared__ float ks[64];
    __shared__ float zs[64];

    const int nh = blockIdx.y;
    const int n  = nh >> 4;
    const int h  = nh & 15;
    const int l0 = blockIdx.x * 64;
    const int t  = threadIdx.x;

    for (int i = t; i < 64 * 16; i += 256) {
        const int r  = i >> 4;
        const int c4 = i & 15;
        float4 v = *(const float4*)(Ql + (size_t)(n * SEQ + l0 + r) * D_MODEL
                                       + h * HD + c4 * 4);
        *(float4*)&Qs[r][c4 * 4] = v;
    }
    for (int i = t; i < 4096; i += 256) {
        const int m = i >> 6;
        const int d = i & 63;
        KVT[d][m] = KV[((size_t)nh * HD + m) * HD + d];
    }
    if (t < 64) ks[t] = KS[nh * HD + t];
    __syncthreads();

    if (t < 64) {
        float a = 0.f;
        #pragma unroll 8
        for (int d = 0; d < 64; d++) a += Qs[t][d] * ks[d];
        zs[t] = 1.f / (a + 1e-10f);
    }
    __syncthreads();

    const int tl = t >> 4;
    const int tm = t & 15;

    ull acc[4][2];
    #pragma unroll
    for (int i = 0; i < 4; i++) { acc[i][0] = 0ull; acc[i][1] = 0ull; }

    #pragma unroll 8
    for (int d = 0; d < 64; d++) {
        const ull kv0 = *(const ull*)&KVT[d][tm * 4];
        const ull kv1 = *(const ull*)&KVT[d][tm * 4 + 2];
        #pragma unroll
        for (int i = 0; i < 4; i++) {
            const ull qd = dup2(Qs[tl * 4 + i][d]);
            fma2(acc[i][0], qd, kv0);
            fma2(acc[i][1], qd, kv1);
        }
    }

    #pragma unroll
    for (int i = 0; i < 4; i++) {
        const int l  = l0 + tl * 4 + i;
        const float z = zs[tl * 4 + i];
        float2 p0 = unpk(acc[i][0]);
        float2 p1 = unpk(acc[i][1]);
        __half2 o0 = __floats2half2_rn(p0.x * z, p0.y * z);
        __half2 o1 = __floats2half2_rn(p1.x * z, p1.y * z);
        uint2 pk;
        pk.x = *(uint32_t*)&o0;
        pk.y = *(uint32_t*)&o1;
        *(uint2*)(Out + (size_t)(n * SEQ + l) * D_MODEL + h * HD + tm * 4) = pk;
    }
}

// ---------------- launch ---------------------------------------------------
extern "C" void kernel_launch(void* const* d_in, const int* in_sizes, int n_in,
                              void* d_out, int out_size)
{
    const float* queries = (const float*)d_in[0];
    const float* keys    = (const float*)d_in[1];
    const float* values  = (const float*)d_in[2];
    const float* Wq = (const float*)d_in[3];
    const float* bq = (const float*)d_in[4];
    const float* Wk = (const float*)d_in[5];
    const float* bk = (const float*)d_in[6];
    const float* Wv = (const float*)d_in[7];
    const float* bv = (const float*)d_in[8];
    const float* Wo = (const float*)d_in[9];
    const float* bo = (const float*)d_in[10];
    float* out = (float*)d_out;

    void *pQ, *pK, *pV, *pKV, *pKS, *pAh;
    void *pWqh, *pWql, *pWkh, *pWkl, *pWvh, *pWvl, *pWoh, *pWol;
    cudaGetSymbolAddress(&pQ,  g_Q);
    cudaGetSymbolAddress(&pK,  g_K);
    cudaGetSymbolAddress(&pV,  g_V);
    cudaGetSymbolAddress(&pKV, g_KV);
    cudaGetSymbolAddress(&pKS, g_KS);
    cudaGetSymbolAddress(&pAh, g_Ah);
    cudaGetSymbolAddress(&pWqh, g_Wqh); cudaGetSymbolAddress(&pWql, g_Wql);
    cudaGetSymbolAddress(&pWkh, g_Wkh); cudaGetSymbolAddress(&pWkl, g_Wkl);
    cudaGetSymbolAddress(&pWvh, g_Wvh); cudaGetSymbolAddress(&pWvl, g_Wvl);
    cudaGetSymbolAddress(&pWoh, g_Woh); cudaGetSymbolAddress(&pWol, g_Wol);

    cudaFuncSetAttribute(gemm_tc, cudaFuncAttributeMaxDynamicSharedMemorySize, SM_TOTAL);

    const int n4 = M_TOTAL * D_MODEL / 4;
    dim3 cw_grid(32, 32), cw_blk(32, 8);
    dim3 gg(D_MODEL / 128, M_TOTAL / 128);    // (8, 128)

    // weight transpose + split (fp16 hi/lo)
    convert_w_kernel<<<cw_grid, cw_blk>>>(Wq, (hf*)pWqh, (hf*)pWql);
    convert_w_kernel<<<cw_grid, cw_blk>>>(Wk, (hf*)pWkh, (hf*)pWkl);
    convert_w_kernel<<<cw_grid, cw_blk>>>(Wv, (hf*)pWvh, (hf*)pWvl);
    convert_w_kernel<<<cw_grid, cw_blk>>>(Wo, (hf*)pWoh, (hf*)pWol);

    // zero attention accumulators
    zero_kernel<<<(NH * HD * HD + 255) / 256, 256>>>((float*)pKV, NH * HD * HD);
    zero_kernel<<<(NH * HD + 255) / 256, 256>>>((float*)pKS, NH * HD);

    // Q projection (elu+1)
    convert_a_kernel<<<(n4 + 255) / 256, 256>>>(queries, (hf*)pAh, n4);
    gemm_tc<<<gg, 256, SM_TOTAL>>>((hf*)pAh, (hf*)pWqh, (hf*)pWql, bq, (float*)pQ, 1);
    // K projection (elu+1)
    convert_a_kernel<<<(n4 + 255) / 256, 256>>>(keys, (hf*)pAh, n4);
    gemm_tc<<<gg, 256, SM_TOTAL>>>((hf*)pAh, (hf*)pWkh, (hf*)pWkl, bk, (float*)pK, 1);
    // V projection
    convert_a_kernel<<<(n4 + 255) / 256, 256>>>(values, (hf*)pAh, n4);
    gemm_tc<<<gg, 256, SM_TOTAL>>>((hf*)pAh, (hf*)pWvh, (hf*)pWvl, bv, (float*)pV, 0);

    // linear attention core (fp32; attn_out emits fp16 A for the Wo GEMM)
    kv_kernel<<<dim3(NH, 8), 256>>>((const float*)pK, (const float*)pV, (float*)pKV);
    ksum_kernel<<<dim3(NH, 8), 64>>>((const float*)pK, (float*)pKS);
    attn_out_kernel<<<dim3(SEQ / 64, NH), 256>>>((const float*)pQ, (const float*)pKV,
                                                 (const float*)pKS, (hf*)pAh);

    // output projection
    gemm_tc<<<gg, 256, SM_TOTAL>>>((hf*)pAh, (hf*)pWoh, (hf*)pWol, bo, out, 0);
}

// round 9
// speedup vs baseline: 3.6805x; 1.3748x over previous
#include <cuda_runtime.h>
#include <cuda_fp16.h>
#include <math.h>
#include <cstdint>

// Problem constants
#define D_MODEL 1024
#define N_BATCH 4
#define SEQ     4096
#define HEADS   16
#define HD      64
#define NH      (N_BATCH * HEADS)        // 64
#define M_TOTAL (N_BATCH * SEQ)          // 16384

typedef unsigned long long ull;
typedef __half hf;

// ---------------- scratch (device globals: no allocation allowed) ----------
__device__ float g_Q [M_TOTAL * D_MODEL];   // Q_lin  (elu+1 applied)
__device__ float g_K [M_TOTAL * D_MODEL];   // K_lin  (elu+1 applied)
__device__ float g_V [M_TOTAL * D_MODEL];   // V projection
__device__ float g_KV[NH * HD * HD];        // per-(n,h) KV[m][d]
__device__ float g_KS[NH * HD];             // per-(n,h) K_sum[d]

// fp16 scratch for tensor-core GEMMs (single-rounded A and W)
__device__ hf g_Ah[M_TOTAL * D_MODEL];
__device__ hf g_Wqh[D_MODEL * D_MODEL];
__device__ hf g_Wkh[D_MODEL * D_MODEL];
__device__ hf g_Wvh[D_MODEL * D_MODEL];
__device__ hf g_Woh[D_MODEL * D_MODEL];

// ---------------- ptx helpers ---------------------------------------------
__device__ __forceinline__ uint32_t smem_u32(const void* p) {
    uint32_t a;
    asm("{ .reg .u64 t; cvta.to.shared.u64 t, %1; cvt.u32.u64 %0, t; }" : "=r"(a) : "l"(p));
    return a;
}
__device__ __forceinline__ void cp_async16(uint32_t s, const void* g) {
    asm volatile("cp.async.cg.shared.global [%0], [%1], 16;" :: "r"(s), "l"(g));
}
__device__ __forceinline__ void cpa_commit() { asm volatile("cp.async.commit_group;" ::: "memory"); }
__device__ __forceinline__ void cpa_wait1()  { asm volatile("cp.async.wait_group 1;" ::: "memory"); }

#define LDSM4(r, a) \
    asm volatile("ldmatrix.sync.aligned.m8n8.x4.shared.b16 {%0,%1,%2,%3}, [%4];" \
        : "=r"((r)[0]), "=r"((r)[1]), "=r"((r)[2]), "=r"((r)[3]) : "r"(a))

#define MMA16816(d, a, b) \
    asm volatile("mma.sync.aligned.m16n8k16.row.col.f32.f16.f16.f32 " \
        "{%0,%1,%2,%3}, {%4,%5,%6,%7}, {%8,%9}, {%0,%1,%2,%3};" \
        : "+f"((d)[0]), "+f"((d)[1]), "+f"((d)[2]), "+f"((d)[3]) \
        : "r"((a)[0]), "r"((a)[1]), "r"((a)[2]), "r"((a)[3]), \
          "r"((b)[0]), "r"((b)[1]))

// ---------------- packed f32x2 helpers (attention core) --------------------
__device__ __forceinline__ void fma2(ull& d, ull a, ull b) {
    asm("fma.rn.f32x2 %0, %1, %2, %3;" : "=l"(d) : "l"(a), "l"(b), "l"(d));
}
__device__ __forceinline__ ull dup2(float x) {
    ull r; asm("mov.b64 %0, {%1, %1};" : "=l"(r) : "f"(x)); return r;
}
__device__ __forceinline__ float2 unpk(ull a) {
    float2 r; asm("mov.b64 {%0, %1}, %2;" : "=f"(r.x), "=f"(r.y) : "l"(a));
    return r;
}

// ================= mma.sync GEMM: C[M,1024] = A[M,1024]*W + bias (+elu+1) ==
// A as fp16 [M,K] row-major; W as transposed fp16 [N,K] row-major.
// Tile: BM=128, BN=128, BK=32, 3-stage cp.async pipeline, 8 warps (2x4),
// 2 CTAs/SM. Plain fp16 MMA (no split), fp32 accumulators.
// Smem rows: 32 fp16 + 8 pad = 80B stride (5x16B, coprime 8 -> ldmatrix
// conflict-free without explicit swizzle).

#define T_ROWB   80
#define T_BYTES  (128 * T_ROWB)          // 10240
#define ST_BYTES (2 * T_BYTES)           // 20480 (Ah, Bh)
#define OFF_AH   0
#define OFF_BH   T_BYTES
#define GSTAGES  3
#define SM_BIAS  (GSTAGES * ST_BYTES)    // 61440
#define SM_TOTAL (SM_BIAS + 512)
#define NCHUNK   (D_MODEL / 32)          // 32

__device__ __forceinline__ void load_stage(
    uint32_t sb, const hf* __restrict__ Ah, const hf* __restrict__ Bh,
    int brow0, int bcol0, int kt, int tid)
{
    const uint32_t st = sb + (uint32_t)(kt % GSTAGES) * ST_BYTES;
    const size_t kof = (size_t)kt * 32;
    #pragma unroll
    for (int v = 0; v < 2; v++) {
        const int idx = v * 256 + tid;
        const int r  = idx >> 2;
        const int cc = idx & 3;
        const uint32_t so = (uint32_t)(r * T_ROWB + cc * 16);
        const size_t gA = (size_t)(brow0 + r) * D_MODEL + kof + cc * 8;
        const size_t gB = (size_t)(bcol0 + r) * D_MODEL + kof + cc * 8;
        cp_async16(st + OFF_AH + so, Ah + gA);
        cp_async16(st + OFF_BH + so, Bh + gB);
    }
}

__global__ __launch_bounds__(256, 2)
void gemm_tc(const hf* __restrict__ Ah, const hf* __restrict__ Bh,
             const float* __restrict__ bias, float* __restrict__ C, int act)
{
    extern __shared__ char smem[];
    const uint32_t sb = smem_u32(smem);
    const int tid  = threadIdx.x;
    const int lane = tid & 31;
    const int w    = tid >> 5;
    const int wm   = w >> 2;         // 0..1  (m direction, 64 rows each)
    const int wn   = w & 3;          // 0..3  (n direction, 32 cols each)
    const int brow0 = blockIdx.y * 128;
    const int bcol0 = blockIdx.x * 128;

    if (tid < 128) ((float*)(smem + SM_BIAS))[tid] = bias[bcol0 + tid];

    float c[4][4][4];
    #pragma unroll
    for (int mi = 0; mi < 4; mi++)
        #pragma unroll
        for (int ni = 0; ni < 4; ni++)
            #pragma unroll
            for (int q = 0; q < 4; q++) c[mi][ni][q] = 0.f;

    // prologue: stages 0..1
    #pragma unroll
    for (int s = 0; s < GSTAGES - 1; s++) {
        load_stage(sb, Ah, Bh, brow0, bcol0, s, tid);
        cpa_commit();
    }

    // precomputed ldmatrix lane offsets (validated in R5/R6)
    const uint32_t a_lrow = (uint32_t)((lane & 15) * T_ROWB + ((lane >> 4) << 4));
    const uint32_t b_lrow = (uint32_t)(((((lane >> 4) & 1) * 8 + (lane & 7)) * T_ROWB)
                                       + (((lane >> 3) & 1) << 4));

    for (int kt = 0; kt < NCHUNK; kt++) {
        cpa_wait1();                 // group kt complete (empty-commit counting)
        __syncthreads();
        if (kt + GSTAGES - 1 < NCHUNK)
            load_stage(sb, Ah, Bh, brow0, bcol0, kt + GSTAGES - 1, tid);
        cpa_commit();                // unconditional: keeps group indexing exact

        const uint32_t st = sb + (uint32_t)(kt % GSTAGES) * ST_BYTES;

        #pragma unroll
        for (int ks = 0; ks < 2; ks++) {
            const uint32_t kb = ks * 32;   // byte offset of k16 step

            uint32_t ah[4][4];
            #pragma unroll
            for (int mi = 0; mi < 4; mi++) {
                const uint32_t ra = st + OFF_AH
                    + (uint32_t)((wm * 64 + mi * 16) * T_ROWB) + a_lrow + kb;
                LDSM4(ah[mi], ra);
            }
            uint32_t bh[4][2];
            #pragma unroll
            for (int bi = 0; bi < 2; bi++) {
                const uint32_t rb = st + OFF_BH
                    + (uint32_t)((wn * 32 + bi * 16) * T_ROWB) + b_lrow + kb;
                uint32_t t4[4];
                LDSM4(t4, rb);
                bh[2 * bi][0] = t4[0]; bh[2 * bi][1] = t4[1];
                bh[2 * bi + 1][0] = t4[2]; bh[2 * bi + 1][1] = t4[3];
            }
            #pragma unroll
            for (int mi = 0; mi < 4; mi++)
                #pragma unroll
                for (int ni = 0; ni < 4; ni++)
                    MMA16816(c[mi][ni], ah[mi], bh[ni]);
        }
    }

    // epilogue
    const float* sbias = (const float*)(smem + SM_BIAS);
    const int r0 = lane >> 2;
    const int c0 = (lane & 3) * 2;
    #pragma unroll
    for (int mi = 0; mi < 4; mi++) {
        const int m = brow0 + wm * 64 + mi * 16 + r0;
        #pragma unroll
        for (int ni = 0; ni < 4; ni++) {
            const int n = wn * 32 + ni * 8 + c0;
            const float b0 = sbias[n], b1 = sbias[n + 1];
            float v0 = c[mi][ni][0] + b0;
            float v1 = c[mi][ni][1] + b1;
            float v2 = c[mi][ni][2] + b0;
            float v3 = c[mi][ni][3] + b1;
            if (act) {
                v0 = (v0 > 0.f) ? (v0 + 1.f) : expf(v0);
                v1 = (v1 > 0.f) ? (v1 + 1.f) : expf(v1);
                v2 = (v2 > 0.f) ? (v2 + 1.f) : expf(v2);
                v3 = (v3 > 0.f) ? (v3 + 1.f) : expf(v3);
            }
            *(float2*)(C + (size_t)m * D_MODEL + bcol0 + n)       = make_float2(v0, v1);
            *(float2*)(C + (size_t)(m + 8) * D_MODEL + bcol0 + n) = make_float2(v2, v3);
        }
    }
}

// ---------------- fp32 -> fp16 (elementwise, for A operands) ---------------
__global__ void convert_a_kernel(const float* __restrict__ X,
                                 hf* __restrict__ H, int n4)
{
    int i = blockIdx.x * blockDim.x + threadIdx.x;
    if (i >= n4) return;
    float4 x = ((const float4*)X)[i];
    __half2 h0 = __floats2half2_rn(x.x, x.y);
    __half2 h1 = __floats2half2_rn(x.z, x.w);
    ((__half2*)H)[2 * i]     = h0;
    ((__half2*)H)[2 * i + 1] = h1;
}

// ---------------- weight transpose: W[K,N] -> WT[N,K] fp16 -----------------
__global__ void convert_w_kernel(const float* __restrict__ W,
                                 hf* __restrict__ TH)
{
    __shared__ float t[32][33];
    const int bn = blockIdx.x * 32;
    const int bk = blockIdx.y * 32;
    const int tx = threadIdx.x, ty = threadIdx.y;   // (32, 8)
    #pragma unroll
    for (int j = 0; j < 32; j += 8)
        t[ty + j][tx] = W[(size_t)(bk + ty + j) * D_MODEL + bn + tx];
    __syncthreads();
    #pragma unroll
    for (int j = 0; j < 32; j += 8) {
        const size_t o = (size_t)(bn + ty + j) * D_MODEL + bk + tx;
        TH[o] = __float2half_rn(t[tx][ty + j]);
    }
}

// ---------------- zero scratch -------------------------------------------
__global__ void zero_kernel(float* p, int n)
{
    int i = blockIdx.x * blockDim.x + threadIdx.x;
    if (i < n) p[i] = 0.f;
}

// ---------------- KV[m][d] = sum_s K[s][d]*V[s][m]; KS[d] = sum_s K[s][d] --
// per (n,h); grid (NH=64, SPLITS=8), 256 threads. ksum fused (K tile in smem).
__global__ void kv_kernel(const float* __restrict__ Kl, const float* __restrict__ Vb,
                          float* __restrict__ KV, float* __restrict__ KS)
{
    __shared__ float Ks[8][64];
    __shared__ float Vs[8][64];

    const int nh = blockIdx.x;
    const int n  = nh >> 4;
    const int h  = nh & 15;
    const int t  = threadIdx.x;
    const int m  = t >> 2;
    const int d0 = (t & 3) << 4;

    const size_t base = (size_t)n * SEQ * D_MODEL + (size_t)h * HD;
    const int s0 = blockIdx.y * 512;

    const int lr = t >> 5;
    const int lc = (t & 31) * 2;

    ull acc[8];
    #pragma unroll
    for (int j = 0; j < 8; j++) acc[j] = 0ull;
    float ksum = 0.f;

    for (int s = s0; s < s0 + 512; s += 8) {
        const float2 kx = *(const float2*)(Kl + base + (size_t)(s + lr) * D_MODEL + lc);
        const float2 vx = *(const float2*)(Vb + base + (size_t)(s + lr) * D_MODEL + lc);
        __syncthreads();
        *(float2*)&Ks[lr][lc] = kx;
        *(float2*)&Vs[lr][lc] = vx;
        __syncthreads();
        if (t < 64) {
            #pragma unroll
            for (int ss = 0; ss < 8; ss++) ksum += Ks[ss][t];
        }
        #pragma unroll
        for (int ss = 0; ss < 8; ss++) {
            const ull vv = dup2(Vs[ss][m]);
            const ull* kp = (const ull*)&Ks[ss][d0];
            #pragma unroll
            for (int j = 0; j < 8; j++) fma2(acc[j], vv, kp[j]);
        }
    }

    float* kvo = KV + ((size_t)nh * HD + m) * HD + d0;
    #pragma unroll
    for (int j = 0; j < 8; j++) {
        float2 p = unpk(acc[j]);
        atomicAdd(kvo + 2 * j,     p.x);
        atomicAdd(kvo + 2 * j + 1, p.y);
    }
    if (t < 64) atomicAdd(&KS[nh * HD + t], ksum);
}

// ---------------- Out[l][m] = Z(l) * sum_d Q[l][d] * KV[m][d] per (n,h) ----
// Writes fp16 directly (becomes the A operand of the Wo GEMM).
__global__ __launch_bounds__(256)
void attn_out_kernel(const float* __restrict__ Ql, const float* __restrict__ KV,
                     const float* __restrict__ KS, hf* __restrict__ Out)
{
    __shared__ float Qs[64][68];
    __shared__ float KVT[64][66];
    __shared__ float ks[64];
    __shared__ float zs[64];

    const int nh = blockIdx.y;
    const int n  = nh >> 4;
    const int h  = nh & 15;
    const int l0 = blockIdx.x * 64;
    const int t  = threadIdx.x;

    for (int i = t; i < 64 * 16; i += 256) {
        const int r  = i >> 4;
        const int c4 = i & 15;
        float4 v = *(const float4*)(Ql + (size_t)(n * SEQ + l0 + r) * D_MODEL
                                       + h * HD + c4 * 4);
        *(float4*)&Qs[r][c4 * 4] = v;
    }
    for (int i = t; i < 4096; i += 256) {
        const int m = i >> 6;
        const int d = i & 63;
        KVT[d][m] = KV[((size_t)nh * HD + m) * HD + d];
    }
    if (t < 64) ks[t] = KS[nh * HD + t];
    __syncthreads();

    if (t < 64) {
        float a = 0.f;
        #pragma unroll 8
        for (int d = 0; d < 64; d++) a += Qs[t][d] * ks[d];
        zs[t] = 1.f / (a + 1e-10f);
    }
    __syncthreads();

    const int tl = t >> 4;
    const int tm = t & 15;

    ull acc[4][2];
    #pragma unroll
    for (int i = 0; i < 4; i++) { acc[i][0] = 0ull; acc[i][1] = 0ull; }

    #pragma unroll 8
    for (int d = 0; d < 64; d++) {
        const ull kv0 = *(const ull*)&KVT[d][tm * 4];
        const ull kv1 = *(const ull*)&KVT[d][tm * 4 + 2];
        #pragma unroll
        for (int i = 0; i < 4; i++) {
            const ull qd = dup2(Qs[tl * 4 + i][d]);
            fma2(acc[i][0], qd, kv0);
            fma2(acc[i][1], qd, kv1);
        }
    }

    #pragma unroll
    for (int i = 0; i < 4; i++) {
        const int l  = l0 + tl * 4 + i;
        const float z = zs[tl * 4 + i];
        float2 p0 = unpk(acc[i][0]);
        float2 p1 = unpk(acc[i][1]);
        __half2 o0 = __floats2half2_rn(p0.x * z, p0.y * z);
        __half2 o1 = __floats2half2_rn(p1.x * z, p1.y * z);
        uint2 pk;
        pk.x = *(uint32_t*)&o0;
        pk.y = *(uint32_t*)&o1;
        *(uint2*)(Out + (size_t)(n * SEQ + l) * D_MODEL + h * HD + tm * 4) = pk;
    }
}

// ---------------- launch ---------------------------------------------------
extern "C" void kernel_launch(void* const* d_in, const int* in_sizes, int n_in,
                              void* d_out, int out_size)
{
    const float* queries = (const float*)d_in[0];
    const float* keys    = (const float*)d_in[1];
    const float* values  = (const float*)d_in[2];
    const float* Wq = (const float*)d_in[3];
    const float* bq = (const float*)d_in[4];
    const float* Wk = (const float*)d_in[5];
    const float* bk = (const float*)d_in[6];
    const float* Wv = (const float*)d_in[7];
    const float* bv = (const float*)d_in[8];
    const float* Wo = (const float*)d_in[9];
    const float* bo = (const float*)d_in[10];
    float* out = (float*)d_out;

    void *pQ, *pK, *pV, *pKV, *pKS, *pAh;
    void *pWqh, *pWkh, *pWvh, *pWoh;
    cudaGetSymbolAddress(&pQ,  g_Q);
    cudaGetSymbolAddress(&pK,  g_K);
    cudaGetSymbolAddress(&pV,  g_V);
    cudaGetSymbolAddress(&pKV, g_KV);
    cudaGetSymbolAddress(&pKS, g_KS);
    cudaGetSymbolAddress(&pAh, g_Ah);
    cudaGetSymbolAddress(&pWqh, g_Wqh);
    cudaGetSymbolAddress(&pWkh, g_Wkh);
    cudaGetSymbolAddress(&pWvh, g_Wvh);
    cudaGetSymbolAddress(&pWoh, g_Woh);

    cudaFuncSetAttribute(gemm_tc, cudaFuncAttributeMaxDynamicSharedMemorySize, SM_TOTAL);

    const int n4 = M_TOTAL * D_MODEL / 4;
    dim3 cw_grid(32, 32), cw_blk(32, 8);
    dim3 gg(D_MODEL / 128, M_TOTAL / 128);    // (8, 128)

    // weight transpose (fp16)
    convert_w_kernel<<<cw_grid, cw_blk>>>(Wq, (hf*)pWqh);
    convert_w_kernel<<<cw_grid, cw_blk>>>(Wk, (hf*)pWkh);
    convert_w_kernel<<<cw_grid, cw_blk>>>(Wv, (hf*)pWvh);
    convert_w_kernel<<<cw_grid, cw_blk>>>(Wo, (hf*)pWoh);

    // zero attention accumulators
    zero_kernel<<<(NH * HD * HD + 255) / 256, 256>>>((float*)pKV, NH * HD * HD);
    zero_kernel<<<(NH * HD + 255) / 256, 256>>>((float*)pKS, NH * HD);

    // Q projection (elu+1)
    convert_a_kernel<<<(n4 + 255) / 256, 256>>>(queries, (hf*)pAh, n4);
    gemm_tc<<<gg, 256, SM_TOTAL>>>((hf*)pAh, (hf*)pWqh, bq, (float*)pQ, 1);
    // K projection (elu+1)
    convert_a_kernel<<<(n4 + 255) / 256, 256>>>(keys, (hf*)pAh, n4);
    gemm_tc<<<gg, 256, SM_TOTAL>>>((hf*)pAh, (hf*)pWkh, bk, (float*)pK, 1);
    // V projection
    convert_a_kernel<<<(n4 + 255) / 256, 256>>>(values, (hf*)pAh, n4);
    gemm_tc<<<gg, 256, SM_TOTAL>>>((hf*)pAh, (hf*)pWvh, bv, (float*)pV, 0);

    // linear attention core (ksum fused into kv)
    kv_kernel<<<dim3(NH, 8), 256>>>((const float*)pK, (const float*)pV,
                                    (float*)pKV, (float*)pKS);
    attn_out_kernel<<<dim3(SEQ / 64, NH), 256>>>((const float*)pQ, (const float*)pKV,
                                                 (const float*)pKS, (hf*)pAh);

    // output projection
    gemm_tc<<<gg, 256, SM_TOTAL>>>((hf*)pAh, (hf*)pWoh, bo, out, 0);
}

// round 11
// speedup vs baseline: 5.9916x; 1.6279x over previous
#include <cuda_runtime.h>
#include <cuda_fp16.h>
#include <math.h>
#include <cstdint>

// Problem constants
#define D_MODEL 1024
#define N_BATCH 4
#define SEQ     4096
#define HEADS   16
#define HD      64
#define NH      (N_BATCH * HEADS)        // 64
#define M_TOTAL (N_BATCH * SEQ)          // 16384

typedef unsigned long long ull;
typedef __half hf;

// ---------------- scratch (device globals: no allocation allowed) ----------
__device__ float g_KV [NH * HD * HD];       // per-(n,h) KV[m][d] fp32 accum
__device__ hf    g_KVh[NH * HD * HD];       // fp16 copy for MMA
__device__ float g_KS [NH * HD];            // per-(n,h) K_sum[d]

__device__ hf g_Ah[M_TOTAL * D_MODEL];      // GEMM A operand / attn output
__device__ hf g_Qh[M_TOTAL * D_MODEL];      // Q_lin fp16 [token][channel]
__device__ hf g_KT[D_MODEL * M_TOTAL];      // K_lin^T fp16 [channel][token]
__device__ hf g_VT[D_MODEL * M_TOTAL];      // V^T     fp16 [channel][token]
__device__ hf g_Wqh[D_MODEL * D_MODEL];
__device__ hf g_Wkh[D_MODEL * D_MODEL];
__device__ hf g_Wvh[D_MODEL * D_MODEL];
__device__ hf g_Woh[D_MODEL * D_MODEL];

// ---------------- ptx helpers ---------------------------------------------
__device__ __forceinline__ uint32_t smem_u32(const void* p) {
    uint32_t a;
    asm("{ .reg .u64 t; cvta.to.shared.u64 t, %1; cvt.u32.u64 %0, t; }" : "=r"(a) : "l"(p));
    return a;
}
__device__ __forceinline__ void cp_async16(uint32_t s, const void* g) {
    asm volatile("cp.async.cg.shared.global [%0], [%1], 16;" :: "r"(s), "l"(g));
}
__device__ __forceinline__ void cpa_commit() { asm volatile("cp.async.commit_group;" ::: "memory"); }
__device__ __forceinline__ void cpa_wait1()  { asm volatile("cp.async.wait_group 1;" ::: "memory"); }
__device__ __forceinline__ void cpa_wait0()  { asm volatile("cp.async.wait_group 0;" ::: "memory"); }

#define LDSM4(r, a) \
    asm volatile("ldmatrix.sync.aligned.m8n8.x4.shared.b16 {%0,%1,%2,%3}, [%4];" \
        : "=r"((r)[0]), "=r"((r)[1]), "=r"((r)[2]), "=r"((r)[3]) : "r"(a))

#define MMA16816(d, a, b) \
    asm volatile("mma.sync.aligned.m16n8k16.row.col.f32.f16.f16.f32 " \
        "{%0,%1,%2,%3}, {%4,%5,%6,%7}, {%8,%9}, {%0,%1,%2,%3};" \
        : "+f"((d)[0]), "+f"((d)[1]), "+f"((d)[2]), "+f"((d)[3]) \
        : "r"((a)[0]), "r"((a)[1]), "r"((a)[2]), "r"((a)[3]), \
          "r"((b)[0]), "r"((b)[1]))

// ldmatrix lane-offset generators (validated R5-R9), parametric in row stride
__device__ __forceinline__ uint32_t a_lane_off(int lane, int rowb) {
    return (uint32_t)((lane & 15) * rowb + ((lane >> 4) << 4));
}
__device__ __forceinline__ uint32_t b_lane_off(int lane, int rowb) {
    return (uint32_t)(((((lane >> 4) & 1) * 8 + (lane & 7)) * rowb)
                      + (((lane >> 3) & 1) << 4));
}

// ================= projection GEMM =========================================
// C[M,1024] = A[M,1024] * W^T + bias, optional elu+1, three output modes:
//   otype 0: fp32 normal (Wo -> d_out)
//   otype 1: fp16 normal (Q_lin)
//   otype 2: fp16 transposed [channel][token] (K_lin^T, V^T)
// BM=BN=128, BK=32, 3-stage cp.async, 8 warps, 2 CTAs/SM.

#define T_ROWB   80
#define T_BYTES  (128 * T_ROWB)          // 10240
#define ST_BYTES (2 * T_BYTES)           // 20480
#define OFF_AH   0
#define OFF_BH   T_BYTES
#define GSTAGES  3
#define SM_BIAS  (GSTAGES * ST_BYTES)    // 61440
#define SM_TOTAL (SM_BIAS + 512)
#define NCHUNK   (D_MODEL / 32)          // 32
#define TR_STRIDE 136                    // transpose buffer halves/row

__device__ __forceinline__ void load_stage(
    uint32_t sb, const hf* __restrict__ Ah, const hf* __restrict__ Bh,
    int brow0, int bcol0, int kt, int tid)
{
    const uint32_t st = sb + (uint32_t)(kt % GSTAGES) * ST_BYTES;
    const size_t kof = (size_t)kt * 32;
    #pragma unroll
    for (int v = 0; v < 2; v++) {
        const int idx = v * 256 + tid;
        const int r  = idx >> 2;
        const int cc = idx & 3;
        const uint32_t so = (uint32_t)(r * T_ROWB + cc * 16);
        const size_t gA = (size_t)(brow0 + r) * D_MODEL + kof + cc * 8;
        const size_t gB = (size_t)(bcol0 + r) * D_MODEL + kof + cc * 8;
        cp_async16(st + OFF_AH + so, Ah + gA);
        cp_async16(st + OFF_BH + so, Bh + gB);
    }
}

__global__ __launch_bounds__(256, 2)
void gemm_tc(const hf* __restrict__ Ah, const hf* __restrict__ Bh,
             const float* __restrict__ bias,
             float* __restrict__ Cf, hf* __restrict__ Ch,
             int act, int otype)
{
    extern __shared__ char smem[];
    const uint32_t sb = smem_u32(smem);
    const int tid  = threadIdx.x;
    const int lane = tid & 31;
    const int w    = tid >> 5;
    const int wm   = w >> 2;         // 0..1
    const int wn   = w & 3;          // 0..3
    const int brow0 = blockIdx.y * 128;
    const int bcol0 = blockIdx.x * 128;

    if (tid < 128) ((float*)(smem + SM_BIAS))[tid] = bias[bcol0 + tid];

    float c[4][4][4];
    #pragma unroll
    for (int mi = 0; mi < 4; mi++)
        #pragma unroll
        for (int ni = 0; ni < 4; ni++)
            #pragma unroll
            for (int q = 0; q < 4; q++) c[mi][ni][q] = 0.f;

    #pragma unroll
    for (int s = 0; s < GSTAGES - 1; s++) {
        load_stage(sb, Ah, Bh, brow0, bcol0, s, tid);
        cpa_commit();
    }

    const uint32_t a_lrow = a_lane_off(lane, T_ROWB);
    const uint32_t b_lrow = b_lane_off(lane, T_ROWB);

    for (int kt = 0; kt < NCHUNK; kt++) {
        cpa_wait1();
        __syncthreads();
        if (kt + GSTAGES - 1 < NCHUNK)
            load_stage(sb, Ah, Bh, brow0, bcol0, kt + GSTAGES - 1, tid);
        cpa_commit();

        const uint32_t st = sb + (uint32_t)(kt % GSTAGES) * ST_BYTES;

        #pragma unroll
        for (int ks = 0; ks < 2; ks++) {
            const uint32_t kb = ks * 32;
            uint32_t ah[4][4];
            #pragma unroll
            for (int mi = 0; mi < 4; mi++) {
                const uint32_t ra = st + OFF_AH
                    + (uint32_t)((wm * 64 + mi * 16) * T_ROWB) + a_lrow + kb;
                LDSM4(ah[mi], ra);
            }
            uint32_t bh[4][2];
            #pragma unroll
            for (int bi = 0; bi < 2; bi++) {
                const uint32_t rb = st + OFF_BH
                    + (uint32_t)((wn * 32 + bi * 16) * T_ROWB) + b_lrow + kb;
                uint32_t t4[4];
                LDSM4(t4, rb);
                bh[2 * bi][0] = t4[0]; bh[2 * bi][1] = t4[1];
                bh[2 * bi + 1][0] = t4[2]; bh[2 * bi + 1][1] = t4[3];
            }
            #pragma unroll
            for (int mi = 0; mi < 4; mi++)
                #pragma unroll
                for (int ni = 0; ni < 4; ni++)
                    MMA16816(c[mi][ni], ah[mi], bh[ni]);
        }
    }

    // ---------------- epilogue ----------------
    const float* sbias = (const float*)(smem + SM_BIAS);
    const int r0 = lane >> 2;
    const int c0 = (lane & 3) * 2;

    if (otype == 2) {
        // transpose via smem, then coalesced fp16 stores to Ch[[chan][tok]]
        __syncthreads();                    // mainloop smem reads done
        hf* TR = (hf*)smem;                 // [128][TR_STRIDE]
        #pragma unroll
        for (int mi = 0; mi < 4; mi++) {
            const int m0 = wm * 64 + mi * 16 + r0;
            #pragma unroll
            for (int ni = 0; ni < 4; ni++) {
                const int n = wn * 32 + ni * 8 + c0;
                const float b0 = sbias[n], b1 = sbias[n + 1];
                float v0 = c[mi][ni][0] + b0;
                float v1 = c[mi][ni][1] + b1;
                float v2 = c[mi][ni][2] + b0;
                float v3 = c[mi][ni][3] + b1;
                if (act) {
                    v0 = (v0 > 0.f) ? (v0 + 1.f) : expf(v0);
                    v1 = (v1 > 0.f) ? (v1 + 1.f) : expf(v1);
                    v2 = (v2 > 0.f) ? (v2 + 1.f) : expf(v2);
                    v3 = (v3 > 0.f) ? (v3 + 1.f) : expf(v3);
                }
                TR[n * TR_STRIDE + m0]           = __float2half_rn(v0);
                TR[(n + 1) * TR_STRIDE + m0]     = __float2half_rn(v1);
                TR[n * TR_STRIDE + m0 + 8]       = __float2half_rn(v2);
                TR[(n + 1) * TR_STRIDE + m0 + 8] = __float2half_rn(v3);
            }
        }
        __syncthreads();
        for (int i = tid; i < 128 * 16; i += 256) {
            const int n = i >> 4, seg = i & 15;
            float4 val = *(float4*)&TR[n * TR_STRIDE + seg * 8];
            *(float4*)(Ch + (size_t)(bcol0 + n) * M_TOTAL + brow0 + seg * 8) = val;
        }
        return;
    }

    #pragma unroll
    for (int mi = 0; mi < 4; mi++) {
        const int m = brow0 + wm * 64 + mi * 16 + r0;
        #pragma unroll
        for (int ni = 0; ni < 4; ni++) {
            const int n = wn * 32 + ni * 8 + c0;
            const float b0 = sbias[n], b1 = sbias[n + 1];
            float v0 = c[mi][ni][0] + b0;
            float v1 = c[mi][ni][1] + b1;
            float v2 = c[mi][ni][2] + b0;
            float v3 = c[mi][ni][3] + b1;
            if (act) {
                v0 = (v0 > 0.f) ? (v0 + 1.f) : expf(v0);
                v1 = (v1 > 0.f) ? (v1 + 1.f) : expf(v1);
                v2 = (v2 > 0.f) ? (v2 + 1.f) : expf(v2);
                v3 = (v3 > 0.f) ? (v3 + 1.f) : expf(v3);
            }
            if (otype == 0) {
                *(float2*)(Cf + (size_t)m * D_MODEL + bcol0 + n)       = make_float2(v0, v1);
                *(float2*)(Cf + (size_t)(m + 8) * D_MODEL + bcol0 + n) = make_float2(v2, v3);
            } else {
                *(__half2*)(Ch + (size_t)m * D_MODEL + bcol0 + n)       = __floats2half2_rn(v0, v1);
                *(__half2*)(Ch + (size_t)(m + 8) * D_MODEL + bcol0 + n) = __floats2half2_rn(v2, v3);
            }
        }
    }
}

// ---------------- fp32 -> fp16 (elementwise, A operands) -------------------
__global__ void convert_a_kernel(const float* __restrict__ X,
                                 hf* __restrict__ H, int n4)
{
    int i = blockIdx.x * blockDim.x + threadIdx.x;
    if (i >= n4) return;
    float4 x = ((const float4*)X)[i];
    ((__half2*)H)[2 * i]     = __floats2half2_rn(x.x, x.y);
    ((__half2*)H)[2 * i + 1] = __floats2half2_rn(x.z, x.w);
}

// ---------------- weight transpose: W[K,N] -> WT[N,K] fp16 -----------------
__global__ void convert_w_kernel(const float* __restrict__ W,
                                 hf* __restrict__ TH)
{
    __shared__ float t[32][33];
    const int bn = blockIdx.x * 32;
    const int bk = blockIdx.y * 32;
    const int tx = threadIdx.x, ty = threadIdx.y;   // (32, 8)
    #pragma unroll
    for (int j = 0; j < 32; j += 8)
        t[ty + j][tx] = W[(size_t)(bk + ty + j) * D_MODEL + bn + tx];
    __syncthreads();
    #pragma unroll
    for (int j = 0; j < 32; j += 8) {
        const size_t o = (size_t)(bn + ty + j) * D_MODEL + bk + tx;
        TH[o] = __float2half_rn(t[tx][ty + j]);
    }
}

// ---------------- zero scratch ---------------------------------------------
__global__ void zero_kernel(float* p, int n)
{
    int i = blockIdx.x * blockDim.x + threadIdx.x;
    if (i < n) p[i] = 0.f;
}

// ---------------- KS[(n,h),d] = sum_s KT[h*64+d][n*4096+s] -----------------
// grid (1024 channels, 4 batches), 128 threads
__global__ void ksum_kernel(const hf* __restrict__ KT, float* __restrict__ KS)
{
    __shared__ float red[4];
    const int row = blockIdx.x;           // global channel = h*64+d
    const int n   = blockIdx.y;
    const int t   = threadIdx.x;
    const float4* p = (const float4*)(KT + (size_t)row * M_TOTAL + n * SEQ);
    float s = 0.f;
    for (int i = t; i < SEQ / 8; i += 128) {
        float4 v = p[i];
        const __half2* h2 = (const __half2*)&v;
        #pragma unroll
        for (int j = 0; j < 4; j++) {
            float2 f = __half22float2(h2[j]);
            s += f.x + f.y;
        }
    }
    #pragma unroll
    for (int o = 16; o > 0; o >>= 1) s += __shfl_down_sync(0xffffffff, s, o);
    if ((t & 31) == 0) red[t >> 5] = s;
    __syncthreads();
    if (t == 0) {
        const int h = row >> 6, d = row & 63;
        KS[((size_t)n * HEADS + h) * HD + d] = red[0] + red[1] + red[2] + red[3];
    }
}

// ---------------- kv_tc: KV[m][d] += sum_s VT[.][s]*KT[.][s] ---------------
// grid (NH=64, SPLIT=8). M=N=64, K=512 per block (8 chunks of 64).
#define KVROWB   144
#define KV_TB    (64 * KVROWB)           // 9216
#define KV_ST    (2 * KV_TB)             // 18432
#define KV_SM    (GSTAGES * KV_ST)       // 55296

__device__ __forceinline__ void kv_load_stage(
    uint32_t sb, const hf* __restrict__ Vp, const hf* __restrict__ Kp,
    int kc, int tid)
{
    const uint32_t st = sb + (uint32_t)(kc % GSTAGES) * KV_ST;
    #pragma unroll
    for (int v = 0; v < 2; v++) {
        const int idx = v * 256 + tid;
        const int r  = idx >> 3;
        const int cc = idx & 7;
        const uint32_t so = (uint32_t)(r * KVROWB + cc * 16);
        const size_t g = (size_t)r * M_TOTAL + kc * 64 + cc * 8;
        cp_async16(st + so,         Vp + g);
        cp_async16(st + KV_TB + so, Kp + g);
    }
}

__global__ __launch_bounds__(256, 2)
void kv_tc(const hf* __restrict__ VT, const hf* __restrict__ KT,
           float* __restrict__ KV)
{
    extern __shared__ char smem[];
    const uint32_t sb = smem_u32(smem);
    const int tid  = threadIdx.x;
    const int lane = tid & 31;
    const int w    = tid >> 5;
    const int wm   = w & 3;          // 4 x 16 rows (m)
    const int wn   = w >> 2;         // 2 x 32 cols (d)
    const int nh = blockIdx.x;
    const int n  = nh >> 4;
    const int h  = nh & 15;
    const int sp = blockIdx.y;

    const hf* Vp = VT + (size_t)(h * HD) * M_TOTAL + n * SEQ + sp * 512;
    const hf* Kp = KT + (size_t)(h * HD) * M_TOTAL + n * SEQ + sp * 512;

    float c[4][4];
    #pragma unroll
    for (int ni = 0; ni < 4; ni++)
        #pragma unroll
        for (int q = 0; q < 4; q++) c[ni][q] = 0.f;

    #pragma unroll
    for (int s = 0; s < GSTAGES - 1; s++) {
        kv_load_stage(sb, Vp, Kp, s, tid);
        cpa_commit();
    }

    const uint32_t a_lrow = a_lane_off(lane, KVROWB);
    const uint32_t b_lrow = b_lane_off(lane, KVROWB);

    for (int kc = 0; kc < 8; kc++) {
        cpa_wait1();
        __syncthreads();
        if (kc + GSTAGES - 1 < 8)
            kv_load_stage(sb, Vp, Kp, kc + GSTAGES - 1, tid);
        cpa_commit();

        const uint32_t st = sb + (uint32_t)(kc % GSTAGES) * KV_ST;
        #pragma unroll
        for (int ks = 0; ks < 4; ks++) {
            const uint32_t kb = ks * 32;
            uint32_t ah[4];
            LDSM4(ah, st + (uint32_t)(wm * 16 * KVROWB) + a_lrow + kb);
            uint32_t bh[4][2];
            #pragma unroll
            for (int bi = 0; bi < 2; bi++) {
                uint32_t t4[4];
                LDSM4(t4, st + KV_TB + (uint32_t)((wn * 32 + bi * 16) * KVROWB)
                          + b_lrow + kb);
                bh[2 * bi][0] = t4[0]; bh[2 * bi][1] = t4[1];
                bh[2 * bi + 1][0] = t4[2]; bh[2 * bi + 1][1] = t4[3];
            }
            #pragma unroll
            for (int ni = 0; ni < 4; ni++)
                MMA16816(c[ni], ah, bh[ni]);
        }
    }

    const int r0 = lane >> 2;
    const int c0 = (lane & 3) * 2;
    const int m  = wm * 16 + r0;
    #pragma unroll
    for (int ni = 0; ni < 4; ni++) {
        const int d = wn * 32 + ni * 8 + c0;
        float* o = KV + ((size_t)nh * HD + m) * HD + d;
        atomicAdd(o,              c[ni][0]);
        atomicAdd(o + 1,          c[ni][1]);
        atomicAdd(o + 8 * HD,     c[ni][2]);
        atomicAdd(o + 8 * HD + 1, c[ni][3]);
    }
}

// ---------------- KV fp32 -> fp16 ------------------------------------------
__global__ void kvh_kernel(const float* __restrict__ KV, hf* __restrict__ KVh)
{
    int i = blockIdx.x * blockDim.x + threadIdx.x;
    float4 v = ((const float4*)KV)[i];
    ((__half2*)KVh)[2 * i]     = __floats2half2_rn(v.x, v.y);
    ((__half2*)KVh)[2 * i + 1] = __floats2half2_rn(v.z, v.w);
}

// ---------------- attn_out_tc: Out[l][h*64+m] = Z(l)*sum_d Q[l][d]*KV[m][d]
// grid (SEQ/128 = 32, NH=64), 256 threads. M=128(l), N=64(m), K=64(d).
__global__ __launch_bounds__(256)
void attn_out_tc(const hf* __restrict__ Qh, const hf* __restrict__ KVh,
                 const float* __restrict__ KS, hf* __restrict__ Out)
{
    __shared__ hf Qs[128 * 72];      // ROWB 144B
    __shared__ hf Bs[64 * 72];
    __shared__ float ks[64];
    __shared__ float zs[128];

    const int tid  = threadIdx.x;
    const int lane = tid & 31;
    const int w    = tid >> 5;
    const int wm   = w >> 1;         // 4 x 32 rows (l)
    const int wn   = w & 1;          // 2 x 32 cols (m)
    const int nh = blockIdx.y;
    const int n  = nh >> 4;
    const int h  = nh & 15;
    const int l0 = blockIdx.x * 128;

    const uint32_t sq = smem_u32(Qs);
    const uint32_t sbv = smem_u32(Bs);

    // Q tile: 128 rows x 64 halves
    #pragma unroll
    for (int v = 0; v < 4; v++) {
        const int idx = v * 256 + tid;
        const int r = idx >> 3, cc = idx & 7;
        cp_async16(sq + (uint32_t)(r * 144 + cc * 16),
                   Qh + (size_t)(n * SEQ + l0 + r) * D_MODEL + h * HD + cc * 8);
    }
    // KV tile: 64 rows x 64 halves
    #pragma unroll
    for (int v = 0; v < 2; v++) {
        const int idx = v * 256 + tid;
        const int r = idx >> 3, cc = idx & 7;
        cp_async16(sbv + (uint32_t)(r * 144 + cc * 16),
                   KVh + ((size_t)nh * HD + r) * HD + cc * 8);
    }
    if (tid < 64) ks[tid] = KS[(size_t)nh * HD + tid];
    cpa_commit();
    cpa_wait0();
    __syncthreads();

    // normalizer
    if (tid < 128) {
        float a = 0.f;
        #pragma unroll 8
        for (int d = 0; d < 64; d++)
            a += __half2float(Qs[tid * 72 + d]) * ks[d];
        zs[tid] = 1.f / (a + 1e-10f);
    }
    __syncthreads();

    const uint32_t a_lrow = a_lane_off(lane, 144);
    const uint32_t b_lrow = b_lane_off(lane, 144);

    float c[2][4][4];
    #pragma unroll
    for (int mi = 0; mi < 2; mi++)
        #pragma unroll
        for (int ni = 0; ni < 4; ni++)
            #pragma unroll
            for (int q = 0; q < 4; q++) c[mi][ni][q] = 0.f;

    #pragma unroll
    for (int ks_ = 0; ks_ < 4; ks_++) {
        const uint32_t kb = ks_ * 32;
        uint32_t ah[2][4];
        #pragma unroll
        for (int mi = 0; mi < 2; mi++)
            LDSM4(ah[mi], sq + (uint32_t)((wm * 32 + mi * 16) * 144) + a_lrow + kb);
        uint32_t bh[4][2];
        #pragma unroll
        for (int bi = 0; bi < 2; bi++) {
            uint32_t t4[4];
            LDSM4(t4, sbv + (uint32_t)((wn * 32 + bi * 16) * 144) + b_lrow + kb);
            bh[2 * bi][0] = t4[0]; bh[2 * bi][1] = t4[1];
            bh[2 * bi + 1][0] = t4[2]; bh[2 * bi + 1][1] = t4[3];
        }
        #pragma unroll
        for (int mi = 0; mi < 2; mi++)
            #pragma unroll
            for (int ni = 0; ni < 4; ni++)
                MMA16816(c[mi][ni], ah[mi], bh[ni]);
    }

    const int r0 = lane >> 2;
    const int c0 = (lane & 3) * 2;
    #pragma unroll
    for (int mi = 0; mi < 2; mi++) {
        const int lloc = wm * 32 + mi * 16 + r0;
        const float z0 = zs[lloc];
        const float z1 = zs[lloc + 8];
        #pragma unroll
        for (int ni = 0; ni < 4; ni++) {
            const int m = wn * 32 + ni * 8 + c0;
            hf* o = Out + (size_t)(n * SEQ + l0 + lloc) * D_MODEL + h * HD + m;
            *(__half2*)o = __floats2half2_rn(c[mi][ni][0] * z0, c[mi][ni][1] * z0);
            *(__half2*)(o + 8 * D_MODEL) =
                __floats2half2_rn(c[mi][ni][2] * z1, c[mi][ni][3] * z1);
        }
    }
}

// ---------------- launch ---------------------------------------------------
extern "C" void kernel_launch(void* const* d_in, const int* in_sizes, int n_in,
                              void* d_out, int out_size)
{
    const float* queries = (const float*)d_in[0];
    const float* keys    = (const float*)d_in[1];
    const float* values  = (const float*)d_in[2];
    const float* Wq = (const float*)d_in[3];
    const float* bq = (const float*)d_in[4];
    const float* Wk = (const float*)d_in[5];
    const float* bk = (const float*)d_in[6];
    const float* Wv = (const float*)d_in[7];
    const float* bv = (const float*)d_in[8];
    const float* Wo = (const float*)d_in[9];
    const float* bo = (const float*)d_in[10];
    float* out = (float*)d_out;

    void *pKV, *pKVh, *pKS, *pAh, *pQh, *pKT, *pVT;
    void *pWqh, *pWkh, *pWvh, *pWoh;
    cudaGetSymbolAddress(&pKV,  g_KV);
    cudaGetSymbolAddress(&pKVh, g_KVh);
    cudaGetSymbolAddress(&pKS,  g_KS);
    cudaGetSymbolAddress(&pAh,  g_Ah);
    cudaGetSymbolAddress(&pQh,  g_Qh);
    cudaGetSymbolAddress(&pKT,  g_KT);
    cudaGetSymbolAddress(&pVT,  g_VT);
    cudaGetSymbolAddress(&pWqh, g_Wqh);
    cudaGetSymbolAddress(&pWkh, g_Wkh);
    cudaGetSymbolAddress(&pWvh, g_Wvh);
    cudaGetSymbolAddress(&pWoh, g_Woh);

    cudaFuncSetAttribute(gemm_tc, cudaFuncAttributeMaxDynamicSharedMemorySize, SM_TOTAL);
    cudaFuncSetAttribute(kv_tc,   cudaFuncAttributeMaxDynamicSharedMemorySize, KV_SM);

    const int n4 = M_TOTAL * D_MODEL / 4;
    dim3 cw_grid(32, 32), cw_blk(32, 8);
    dim3 gg(D_MODEL / 128, M_TOTAL / 128);    // (8, 128)

    // weight transpose (fp16)
    convert_w_kernel<<<cw_grid, cw_blk>>>(Wq, (hf*)pWqh);
    convert_w_kernel<<<cw_grid, cw_blk>>>(Wk, (hf*)pWkh);
    convert_w_kernel<<<cw_grid, cw_blk>>>(Wv, (hf*)pWvh);
    convert_w_kernel<<<cw_grid, cw_blk>>>(Wo, (hf*)pWoh);

    // zero KV accumulator
    zero_kernel<<<(NH * HD * HD + 255) / 256, 256>>>((float*)pKV, NH * HD * HD);

    // Q projection: elu+1, fp16 normal
    convert_a_kernel<<<(n4 + 255) / 256, 256>>>(queries, (hf*)pAh, n4);
    gemm_tc<<<gg, 256, SM_TOTAL>>>((hf*)pAh, (hf*)pWqh, bq, nullptr, (hf*)pQh, 1, 1);
    // K projection: elu+1, fp16 transposed
    convert_a_kernel<<<(n4 + 255) / 256, 256>>>(keys, (hf*)pAh, n4);
    gemm_tc<<<gg, 256, SM_TOTAL>>>((hf*)pAh, (hf*)pWkh, bk, nullptr, (hf*)pKT, 1, 2);
    // V projection: fp16 transposed
    convert_a_kernel<<<(n4 + 255) / 256, 256>>>(values, (hf*)pAh, n4);
    gemm_tc<<<gg, 256, SM_TOTAL>>>((hf*)pAh, (hf*)pWvh, bv, nullptr, (hf*)pVT, 0, 2);

    // attention core (tensor-core)
    ksum_kernel<<<dim3(D_MODEL, N_BATCH), 128>>>((const hf*)pKT, (float*)pKS);
    kv_tc<<<dim3(NH, 8), 256, KV_SM>>>((const hf*)pVT, (const hf*)pKT, (float*)pKV);
    kvh_kernel<<<NH * HD * HD / 1024, 256>>>((const float*)pKV, (hf*)pKVh);
    attn_out_tc<<<dim3(SEQ / 128, NH), 256>>>((const hf*)pQh, (const hf*)pKVh,
                                              (const float*)pKS, (hf*)pAh);

    // output projection (fp32 out)
    gemm_tc<<<gg, 256, SM_TOTAL>>>((hf*)pAh, (hf*)pWoh, bo, out, nullptr, 0, 0);
}